// round 10
// baseline (speedup 1.0000x reference)
#include <cuda_runtime.h>
#include <cuda_bf16.h>
#include <math.h>
#include <stdint.h>

// Problem constants (fixed shapes per reference)
#define T_DIM 4096
#define D_DIM 1024
#define BM    64
#define BN    64
#define BK    128                   // bf16 elems per k-tile (256B per row)
#define NT    (D_DIM / BK)          // 8 k-tiles
#define NTILE (T_DIM / BM)          // 64

#define OP_BYTES   (64 * 256)       // one MH tile: 64 rows x 256B
#define B_OFF      OP_BYTES
#define STAGE_BYTES (2 * OP_BYTES)  // 32768 (A-MH + B-MH)
#define NSTAGE 3

#define AUX_OFF   (NSTAGE * STAGE_BYTES)    // 98304
#define KEYI_OFF  (AUX_OFF)                 // 64*8 = 512
#define KEYJ_OFF  (AUX_OFF + 512)           // 64*8 = 512
#define AMJ_OFF   (AUX_OFF + 1024)          // 64*4 = 256
#define AUX_BYTES 1280
#define SMEM_REQ  (AUX_OFF + AUX_BYTES + 1008)

// ---------------- scratch (static device allocations; no cudaMalloc) -------
__device__ __nv_bfloat16 g_MH [T_DIM * D_DIM];
__device__ int                g_am[T_DIM];
__device__ unsigned long long g_rowmin[T_DIM];
__device__ double             g_msep[T_DIM];      // per-row mse partials
__device__ double             g_rowlossp[T_DIM];  // per-row norm partials

// ---------------- helpers ---------------------------------------------------
__device__ __forceinline__ unsigned long long pack_key(float s, int idx) {
    unsigned int u = __float_as_uint(s);
    u = (u & 0x80000000u) ? ~u : (u | 0x80000000u);   // order-preserving float->uint
    return ((unsigned long long)u << 32) | (unsigned int)idx;
}
__device__ __forceinline__ unsigned long long ullmin2(unsigned long long a, unsigned long long b) {
    return a < b ? a : b;
}
__device__ __forceinline__ void mma16816(float* c, const unsigned* a, const unsigned* b) {
    asm volatile(
        "mma.sync.aligned.m16n8k16.row.col.f32.bf16.bf16.f32 "
        "{%0,%1,%2,%3}, {%4,%5,%6,%7}, {%8,%9}, {%0,%1,%2,%3};"
        : "+f"(c[0]), "+f"(c[1]), "+f"(c[2]), "+f"(c[3])
        : "r"(a[0]), "r"(a[1]), "r"(a[2]), "r"(a[3]), "r"(b[0]), "r"(b[1]));
}
__device__ __forceinline__ void ldsm_x4(unsigned* r, unsigned addr) {
    asm volatile("ldmatrix.sync.aligned.m8n8.x4.shared.b16 {%0,%1,%2,%3}, [%4];"
        : "=r"(r[0]), "=r"(r[1]), "=r"(r[2]), "=r"(r[3]) : "r"(addr));
}
__device__ __forceinline__ void cp_async16(unsigned saddr, const void* gaddr) {
    asm volatile("cp.async.cg.shared.global [%0], [%1], 16;" :: "r"(saddr), "l"(gaddr));
}
__device__ __forceinline__ void cp_commit() { asm volatile("cp.async.commit_group;"); }
__device__ __forceinline__ void cp_wait1()  { asm volatile("cp.async.wait_group 1;"); }
__device__ __forceinline__ void cp_wait0()  { asm volatile("cp.async.wait_group 0;"); }

__device__ __forceinline__ unsigned hne2z(unsigned a) {        // 1.0 where != 0
    __nv_bfloat162 va = *reinterpret_cast<__nv_bfloat162*>(&a);
    __nv_bfloat162 z; *reinterpret_cast<unsigned*>(&z) = 0u;
    __nv_bfloat162 r = __hne2(va, z);
    return *reinterpret_cast<unsigned*>(&r);
}
__device__ __forceinline__ unsigned hadd2u(unsigned a, unsigned b) {
    __nv_bfloat162 va = *reinterpret_cast<__nv_bfloat162*>(&a);
    __nv_bfloat162 vb = *reinterpret_cast<__nv_bfloat162*>(&b);
    __nv_bfloat162 r = __hadd2(va, vb);
    return *reinterpret_cast<unsigned*>(&r);
}
__device__ __forceinline__ unsigned hsub2u(unsigned a, unsigned b) {
    __nv_bfloat162 va = *reinterpret_cast<__nv_bfloat162*>(&a);
    __nv_bfloat162 vb = *reinterpret_cast<__nv_bfloat162*>(&b);
    __nv_bfloat162 r = __hsub2(va, vb);
    return *reinterpret_cast<unsigned*>(&r);
}
__device__ __forceinline__ unsigned hmul2u(unsigned a, unsigned b) {
    __nv_bfloat162 va = *reinterpret_cast<__nv_bfloat162*>(&a);
    __nv_bfloat162 vb = *reinterpret_cast<__nv_bfloat162*>(&b);
    __nv_bfloat162 r = __hmul2(va, vb);
    return *reinterpret_cast<unsigned*>(&r);
}

// swizzled byte offset within one 64x256B tile (chunk c in 0..15, row r)
__device__ __forceinline__ unsigned swz(int c, int r) {
    return (((unsigned)((c & 7) ^ (r & 7))) << 4) + ((unsigned)(c >> 3) << 7);
}

// ---------------- kernel 1: build bf16 MH, am[], row-min init, mse partial --
__global__ void prep_kernel(const float* __restrict__ X, const float* __restrict__ H,
                            const float* __restrict__ C, const float* __restrict__ M) {
    int i = blockIdx.x;
    int t = threadIdx.x;                       // 256 threads, 4 elems each
    const size_t base = (size_t)i * D_DIM;
    float4 m4 = *(const float4*)(M + base + t * 4);
    float4 h4 = *(const float4*)(H + base + t * 4);
    float4 x4 = *(const float4*)(X + base + t * 4);
    float4 c4 = *(const float4*)(C + base + t * 4);

    float mv[4] = {m4.x, m4.y, m4.z, m4.w};
    float hv[4] = {h4.x, h4.y, h4.z, h4.w};
    float xv[4] = {x4.x, x4.y, x4.z, x4.w};
    float cv[4] = {c4.x, c4.y, c4.z, c4.w};

    __nv_bfloat16 oh[4];
    float bestv = 3.4e38f; int besti = 0;
    float msum = 0.f;
    #pragma unroll
    for (int q = 0; q < 4; q++) {
        float mb = (mv[q] > 0.f) ? 1.f : 0.f;
        oh[q] = __float2bfloat16(mb * hv[q]);
        float e = (xv[q] - (hv[q] - cv[q])) * mv[q];
        msum += e * e;
        if (mv[q] < bestv) { bestv = mv[q]; besti = t * 4 + q; }
    }
    *(uint2*)(g_MH + base + t * 4) = *(uint2*)oh;

    __shared__ float sv[256]; __shared__ int si[256]; __shared__ float ss[256];
    sv[t] = bestv; si[t] = besti; ss[t] = msum;
    __syncthreads();
    for (int o = 128; o > 0; o >>= 1) {
        if (t < o) {
            if (sv[t + o] < sv[t] || (sv[t + o] == sv[t] && si[t + o] < si[t])) {
                sv[t] = sv[t + o]; si[t] = si[t + o];
            }
            ss[t] += ss[t + o];
        }
        __syncthreads();
    }
    if (t == 0) {
        g_am[i] = si[0];
        g_msep[i] = (double)ss[0];
        g_rowmin[i] = pack_key(9999.0f, 0);    // sentinel for argmin kernel
    }
}

// ---------------- kernel 2: MH-only fused GEMM + score argmin ---------------
// All operands derived from MH in registers:
//   Mb = hne2(MH,0), MH2 = MH*MH, PS = MH+Mb, MS = MH-Mb
// accN = Mb.Mb^T                  accG = MH.MH^T
// accP = PS.MS^T             =>   s1 = G - n - P
// accQ = MH2.Mb^T + Mb.MH2^T =>   s2 = Q - 2G
extern __shared__ char dynsmem[];

__global__ __launch_bounds__(128, 2)
void gemm_kernel() {
    // exact triangular cover: grid (NTILE+1, NTILE/2); rows y and NTILE-1-y
    // have lengths (NTILE-y)+(y+1) = NTILE+1, packed into one grid row.
    int bi, bj;
    {
        int x = blockIdx.x, y = blockIdx.y;
        int len0 = NTILE - y;
        if (x < len0) { bi = y;             bj = y + x; }
        else          { bi = NTILE - 1 - y; bj = bi + (x - len0); }
    }

    const int tid  = threadIdx.x;
    const int lane = tid & 31;
    const int warp = tid >> 5;                  // 0..3
    const int wm = warp >> 1;                   // 0..1 -> 32-row slab
    const int wn = warp & 1;                    // 0..1 -> 32-col slab
    const int g  = lane >> 2;
    const int tg = lane & 3;
    const int ib = bi * BM, jb = bj * BN;

    unsigned raw = (unsigned)__cvta_generic_to_shared(dynsmem);
    unsigned sb0 = (raw + 1023u) & ~1023u;      // 1024-aligned stage area
    char* auxg = dynsmem + (sb0 - raw);
    unsigned long long* keyI = (unsigned long long*)(auxg + KEYI_OFF);
    unsigned long long* keyJ = (unsigned long long*)(auxg + KEYJ_OFF);
    int* s_amJ = (int*)(auxg + AMJ_OFF);

    if (tid < BM)            keyI[tid] = ~0ull;
    else {                   keyJ[tid - BM] = ~0ull; s_amJ[tid - BM] = g_am[jb + tid - BM]; }

    float accN[2][4][4], accG[2][4][4], accP[2][4][4], accQ[2][4][4];
    #pragma unroll
    for (int a = 0; a < 2; a++)
        #pragma unroll
        for (int b = 0; b < 4; b++)
            #pragma unroll
            for (int c = 0; c < 4; c++) {
                accN[a][b][c] = 0.f; accG[a][b][c] = 0.f;
                accP[a][b][c] = 0.f; accQ[a][b][c] = 0.f;
            }

    // ---- stage loader: 2 MH tiles (A rows=ib, B rows=jb) x 64 rows x 16 chunks
    auto load_stage = [&](int stage, int kt) {
        unsigned sb = sb0 + stage * STAGE_BYTES;
        int kcol = kt * BK;
        #pragma unroll
        for (int it = 0; it < 16; it++) {          // 2*64*16 = 2048 chunks / 128 thr
            int id = tid + it * 128;
            int op = id >> 10;                     // 0..1
            int rem = id & 1023, r = rem >> 4, c = rem & 15;
            int rowbase = op ? jb : ib;
            const __nv_bfloat16* gp = g_MH + (size_t)(rowbase + r) * D_DIM + kcol + c * 8;
            cp_async16(sb + op * OP_BYTES + r * 256 + swz(c, r), gp);
        }
    };

    // ldmatrix per-lane geometry
    const int a_lrow = lane & 15;
    const int a_half = lane >> 4;
    const int b_lrow = (lane & 7) + ((lane >> 4) << 3);
    const int b_half = (lane >> 3) & 1;

    load_stage(0, 0); cp_commit();
    load_stage(1, 1); cp_commit();

    #pragma unroll 1
    for (int kt = 0; kt < NT; kt++) {
        if (kt < NT - 1) cp_wait1(); else cp_wait0();   // stage kt resident
        __syncthreads();                                 // kt-1 consumption done
        if (kt + 2 < NT) { load_stage((kt + 2) % NSTAGE, kt + 2); cp_commit(); }

        unsigned sb = sb0 + (kt % NSTAGE) * STAGE_BYTES;
        #pragma unroll
        for (int kk8 = 0; kk8 < 16; kk8 += 2) {      // 8 k-chunks of 16
            // ---- all 4 ldsm issued back-to-back (MLP=4 on smem loads) ------
            unsigned br0[4], br1[4], aMH0[4], aMH1[4];
            {
                int row0 = wn * 32 + b_lrow;
                int row1 = wn * 32 + 16 + b_lrow;
                ldsm_x4(br0, sb + B_OFF + row0 * 256 + swz(kk8 + b_half, row0));
                ldsm_x4(br1, sb + B_OFF + row1 * 256 + swz(kk8 + b_half, row1));
                int ar0 = wm * 32 + a_lrow;
                int ar1 = wm * 32 + 16 + a_lrow;
                ldsm_x4(aMH0, sb + ar0 * 256 + swz(kk8 + a_half, ar0));
                ldsm_x4(aMH1, sb + ar1 * 256 + swz(kk8 + a_half, ar1));
            }
            unsigned bMH[4][2];
            bMH[0][0] = br0[0]; bMH[0][1] = br0[1];
            bMH[1][0] = br0[2]; bMH[1][1] = br0[3];
            bMH[2][0] = br1[0]; bMH[2][1] = br1[1];
            bMH[3][0] = br1[2]; bMH[3][1] = br1[3];

            unsigned bMb[4][2], bMH2[4][2], bMS[4][2];
            #pragma unroll
            for (int nf = 0; nf < 4; nf++)
                #pragma unroll
                for (int rr = 0; rr < 2; rr++) {
                    unsigned mh = bMH[nf][rr];
                    unsigned mb = hne2z(mh);
                    bMb[nf][rr]  = mb;
                    bMS[nf][rr]  = hsub2u(mh, mb);
                    bMH2[nf][rr] = hmul2u(mh, mh);
                }
            // A fragments per mf row-slab
            #pragma unroll
            for (int mf = 0; mf < 2; mf++) {
                const unsigned* aMH = mf ? aMH1 : aMH0;
                unsigned aMb[4], aPS[4], aMH2[4];
                #pragma unroll
                for (int q = 0; q < 4; q++) {
                    aMb[q]  = hne2z(aMH[q]);
                    aPS[q]  = hadd2u(aMH[q], aMb[q]);
                    aMH2[q] = hmul2u(aMH[q], aMH[q]);
                }
                #pragma unroll
                for (int nf = 0; nf < 4; nf++) {
                    mma16816(accN[mf][nf], aMb,  bMb[nf]);    // n += Mb.Mb
                    mma16816(accG[mf][nf], aMH,  bMH[nf]);    // G += MH.MH
                    mma16816(accP[mf][nf], aPS,  bMS[nf]);    // P += (MH+Mb).(MH-Mb)
                    mma16816(accQ[mf][nf], aMb,  bMH2[nf]);   // Q += Mb.MH2
                    mma16816(accQ[mf][nf], aMH2, bMb[nf]);    // Q += MH2.Mb
                }
            }
        }
    }

    // ---- epilogue: score + packed (score,index) min-reduction --------------
    unsigned long long rk[2][2] = {{~0ull, ~0ull}, {~0ull, ~0ull}};   // [mf][rr]
    unsigned long long ck[4][2] = {{~0ull,~0ull},{~0ull,~0ull},{~0ull,~0ull},{~0ull,~0ull}};

    #pragma unroll
    for (int mf = 0; mf < 2; mf++) {
        const int i0 = ib + wm * 32 + mf * 16 + g;
        const int am0 = g_am[i0];
        const int am1 = g_am[i0 + 8];
        #pragma unroll
        for (int nf = 0; nf < 4; nf++)
            #pragma unroll
            for (int idx = 0; idx < 4; idx++) {
                int rr = idx >> 1, c = idx & 1;
                int i = i0 + rr * 8;
                int jl = wn * 32 + nf * 8 + tg * 2 + c;
                int j = jb + jl;
                float nn = accN[mf][nf][idx];
                int ami = rr ? am1 : am0;
                if (i != j && nn > 1.5f && ami != s_amJ[jl]) {
                    float ns = fmaxf(nn, 2.f);
                    float gg = accG[mf][nf][idx];
                    float s1 = gg - nn - accP[mf][nf][idx];
                    float s2 = accQ[mf][nf][idx] - 2.f * gg;
                    float var = (s2 - s1 * s1 / ns) / (ns - 1.f);
                    rk[mf][rr] = ullmin2(rk[mf][rr], pack_key(var, j));
                    ck[nf][c]  = ullmin2(ck[nf][c],  pack_key(var, i));
                }
            }
    }

    // row-side: min over quad lanes (same row, different cols)
    #pragma unroll
    for (int mf = 0; mf < 2; mf++)
        #pragma unroll
        for (int rr = 0; rr < 2; rr++) {
            unsigned long long v = rk[mf][rr];
            v = ullmin2(v, __shfl_xor_sync(0xffffffffu, v, 1));
            v = ullmin2(v, __shfl_xor_sync(0xffffffffu, v, 2));
            if (tg == 0 && v != ~0ull)
                atomicMin(&keyI[wm * 32 + mf * 16 + rr * 8 + g], v);
        }
    // col-side: min over lanes sharing tg (same cols, different rows)
    #pragma unroll
    for (int nf = 0; nf < 4; nf++)
        #pragma unroll
        for (int c = 0; c < 2; c++) {
            unsigned long long v = ck[nf][c];
            v = ullmin2(v, __shfl_down_sync(0xffffffffu, v, 4));
            v = ullmin2(v, __shfl_down_sync(0xffffffffu, v, 8));
            v = ullmin2(v, __shfl_down_sync(0xffffffffu, v, 16));
            if (g == 0 && v != ~0ull)
                atomicMin(&keyJ[wn * 32 + nf * 8 + tg * 2 + c], v);
        }

    __syncthreads();
    if (tid < BM) {
        if (keyI[tid] != ~0ull) atomicMin(&g_rowmin[ib + tid], keyI[tid]);
    } else {
        if (keyJ[tid - BM] != ~0ull) atomicMin(&g_rowmin[jb + tid - BM], keyJ[tid - BM]);
    }
}

// ---------------- kernel 3: row loss, warp-per-row ---------------------------
__global__ void rowloss_kernel(const float* __restrict__ H) {
    int warp = threadIdx.x >> 5;                   // 4 warps/block
    int lane = threadIdx.x & 31;
    int i = blockIdx.x * 4 + warp;
    int j = (int)(g_rowmin[i] & 0xFFFFFFFFull);
    const float* ri = H + (size_t)i * D_DIM;
    const float* rj = H + (size_t)j * D_DIM;
    float s = 0.f;
    #pragma unroll
    for (int it = 0; it < 8; it++) {               // 8 x 32 lanes x float4 = 1024
        float4 va = *(const float4*)(ri + it * 128 + lane * 4);
        float4 vb = *(const float4*)(rj + it * 128 + lane * 4);
        float dx = va.x - vb.x, dy = va.y - vb.y, dz = va.z - vb.z, dw = va.w - vb.w;
        s += dx * dx + dy * dy + dz * dz + dw * dw;
    }
    #pragma unroll
    for (int off = 16; off > 0; off >>= 1)
        s += __shfl_xor_sync(0xffffffffu, s, off);
    if (lane == 0) g_rowlossp[i] = sqrt((double)s);
}

// ---------------- kernel 4: combine (deterministic partial sums) -------------
__global__ void final_kernel(float* out) {
    int t = threadIdx.x;                           // 256 threads
    double sm = 0.0, sr = 0.0;
    for (int k = t; k < T_DIM; k += 256) { sm += g_msep[k]; sr += g_rowlossp[k]; }
    __shared__ double shm[256], shr[256];
    shm[t] = sm; shr[t] = sr;
    __syncthreads();
    for (int o = 128; o > 0; o >>= 1) {
        if (t < o) { shm[t] += shm[t + o]; shr[t] += shr[t + o]; }
        __syncthreads();
    }
    if (t == 0) out[0] = (float)(shm[0] + 10.0 * shr[0]);
}

// ---------------- launch ------------------------------------------------------
extern "C" void kernel_launch(void* const* d_in, const int* in_sizes, int n_in,
                              void* d_out, int out_size) {
    const float* X = (const float*)d_in[0];
    const float* H = (const float*)d_in[1];
    const float* C = (const float*)d_in[2];
    const float* M = (const float*)d_in[3];
    (void)in_sizes; (void)n_in; (void)out_size;

    cudaFuncSetAttribute(gemm_kernel, cudaFuncAttributeMaxDynamicSharedMemorySize, SMEM_REQ);

    prep_kernel<<<T_DIM, 256>>>(X, H, C, M);
    dim3 grid(NTILE + 1, NTILE / 2);               // (65, 32) exact triangle cover
    gemm_kernel<<<grid, 128, SMEM_REQ>>>();
    rowloss_kernel<<<T_DIM / 4, 128>>>(H);
    final_kernel<<<1, 256>>>((float*)d_out);
}

// round 11
// speedup vs baseline: 1.0047x; 1.0047x over previous
#include <cuda_runtime.h>
#include <cuda_bf16.h>
#include <math.h>
#include <stdint.h>

// Problem constants (fixed shapes per reference)
#define T_DIM 4096
#define D_DIM 1024
#define BM    64
#define BN    64
#define BK    128                   // bf16 elems per k-tile (256B per row)
#define NT    (D_DIM / BK)          // 8 k-tiles
#define NTILE (T_DIM / BM)          // 64

#define OP_BYTES   (64 * 256)       // one MH tile: 64 rows x 256B
#define B_OFF      OP_BYTES
#define STAGE_BYTES (2 * OP_BYTES)  // 32768 (A-MH + B-MH)
#define NSTAGE 3

#define AUX_OFF   (NSTAGE * STAGE_BYTES)    // 98304
#define KEYI_OFF  (AUX_OFF)                 // 64*8 = 512
#define KEYJ_OFF  (AUX_OFF + 512)           // 64*8 = 512
#define AMJ_OFF   (AUX_OFF + 1024)          // 64*4 = 256
#define AUX_BYTES 1280
#define SMEM_REQ  (AUX_OFF + AUX_BYTES + 1008)

// ---------------- scratch (static device allocations; no cudaMalloc) -------
__device__ __nv_bfloat16 g_MH [T_DIM * D_DIM];
__device__ int                g_am[T_DIM];
__device__ unsigned long long g_rowmin[T_DIM];
__device__ double             g_msep[T_DIM];      // per-row mse partials
__device__ double             g_rowlossp[T_DIM];  // per-row norm partials

// ---------------- helpers ---------------------------------------------------
__device__ __forceinline__ unsigned long long pack_key(float s, int idx) {
    unsigned int u = __float_as_uint(s);
    u = (u & 0x80000000u) ? ~u : (u | 0x80000000u);   // order-preserving float->uint
    return ((unsigned long long)u << 32) | (unsigned int)idx;
}
__device__ __forceinline__ unsigned long long ullmin2(unsigned long long a, unsigned long long b) {
    return a < b ? a : b;
}
__device__ __forceinline__ void mma16816(float* c, const unsigned* a, const unsigned* b) {
    asm volatile(
        "mma.sync.aligned.m16n8k16.row.col.f32.bf16.bf16.f32 "
        "{%0,%1,%2,%3}, {%4,%5,%6,%7}, {%8,%9}, {%0,%1,%2,%3};"
        : "+f"(c[0]), "+f"(c[1]), "+f"(c[2]), "+f"(c[3])
        : "r"(a[0]), "r"(a[1]), "r"(a[2]), "r"(a[3]), "r"(b[0]), "r"(b[1]));
}
__device__ __forceinline__ void ldsm_x4(unsigned* r, unsigned addr) {
    asm volatile("ldmatrix.sync.aligned.m8n8.x4.shared.b16 {%0,%1,%2,%3}, [%4];"
        : "=r"(r[0]), "=r"(r[1]), "=r"(r[2]), "=r"(r[3]) : "r"(addr));
}
__device__ __forceinline__ void cp_async16(unsigned saddr, const void* gaddr) {
    asm volatile("cp.async.cg.shared.global [%0], [%1], 16;" :: "r"(saddr), "l"(gaddr));
}
__device__ __forceinline__ void cp_commit() { asm volatile("cp.async.commit_group;"); }
__device__ __forceinline__ void cp_wait1()  { asm volatile("cp.async.wait_group 1;"); }
__device__ __forceinline__ void cp_wait0()  { asm volatile("cp.async.wait_group 0;"); }

__device__ __forceinline__ unsigned hne2z(unsigned a) {        // 1.0 where != 0
    __nv_bfloat162 va = *reinterpret_cast<__nv_bfloat162*>(&a);
    __nv_bfloat162 z; *reinterpret_cast<unsigned*>(&z) = 0u;
    __nv_bfloat162 r = __hne2(va, z);
    return *reinterpret_cast<unsigned*>(&r);
}
__device__ __forceinline__ unsigned hadd2u(unsigned a, unsigned b) {
    __nv_bfloat162 va = *reinterpret_cast<__nv_bfloat162*>(&a);
    __nv_bfloat162 vb = *reinterpret_cast<__nv_bfloat162*>(&b);
    __nv_bfloat162 r = __hadd2(va, vb);
    return *reinterpret_cast<unsigned*>(&r);
}
__device__ __forceinline__ unsigned hsub2u(unsigned a, unsigned b) {
    __nv_bfloat162 va = *reinterpret_cast<__nv_bfloat162*>(&a);
    __nv_bfloat162 vb = *reinterpret_cast<__nv_bfloat162*>(&b);
    __nv_bfloat162 r = __hsub2(va, vb);
    return *reinterpret_cast<unsigned*>(&r);
}
__device__ __forceinline__ unsigned hmul2u(unsigned a, unsigned b) {
    __nv_bfloat162 va = *reinterpret_cast<__nv_bfloat162*>(&a);
    __nv_bfloat162 vb = *reinterpret_cast<__nv_bfloat162*>(&b);
    __nv_bfloat162 r = __hmul2(va, vb);
    return *reinterpret_cast<unsigned*>(&r);
}

// swizzled byte offset within one 64x256B tile (chunk c in 0..15, row r)
__device__ __forceinline__ unsigned swz(int c, int r) {
    return (((unsigned)((c & 7) ^ (r & 7))) << 4) + ((unsigned)(c >> 3) << 7);
}

// ---------------- kernel 1: build bf16 MH, am[], row-min init, mse partial --
__global__ void prep_kernel(const float* __restrict__ X, const float* __restrict__ H,
                            const float* __restrict__ C, const float* __restrict__ M) {
    int i = blockIdx.x;
    int t = threadIdx.x;                       // 256 threads, 4 elems each
    const size_t base = (size_t)i * D_DIM;
    float4 m4 = *(const float4*)(M + base + t * 4);
    float4 h4 = *(const float4*)(H + base + t * 4);
    float4 x4 = *(const float4*)(X + base + t * 4);
    float4 c4 = *(const float4*)(C + base + t * 4);

    float mv[4] = {m4.x, m4.y, m4.z, m4.w};
    float hv[4] = {h4.x, h4.y, h4.z, h4.w};
    float xv[4] = {x4.x, x4.y, x4.z, x4.w};
    float cv[4] = {c4.x, c4.y, c4.z, c4.w};

    __nv_bfloat16 oh[4];
    float bestv = 3.4e38f; int besti = 0;
    float msum = 0.f;
    #pragma unroll
    for (int q = 0; q < 4; q++) {
        float mb = (mv[q] > 0.f) ? 1.f : 0.f;
        oh[q] = __float2bfloat16(mb * hv[q]);
        float e = (xv[q] - (hv[q] - cv[q])) * mv[q];
        msum += e * e;
        if (mv[q] < bestv) { bestv = mv[q]; besti = t * 4 + q; }
    }
    *(uint2*)(g_MH + base + t * 4) = *(uint2*)oh;

    __shared__ float sv[256]; __shared__ int si[256]; __shared__ float ss[256];
    sv[t] = bestv; si[t] = besti; ss[t] = msum;
    __syncthreads();
    for (int o = 128; o > 0; o >>= 1) {
        if (t < o) {
            if (sv[t + o] < sv[t] || (sv[t + o] == sv[t] && si[t + o] < si[t])) {
                sv[t] = sv[t + o]; si[t] = si[t + o];
            }
            ss[t] += ss[t + o];
        }
        __syncthreads();
    }
    if (t == 0) {
        g_am[i] = si[0];
        g_msep[i] = (double)ss[0];
        g_rowmin[i] = pack_key(9999.0f, 0);    // sentinel for argmin kernel
    }
}

// ---------------- kernel 2: MH-only fused GEMM + score argmin ---------------
// All operands derived from MH in registers:
//   Mb = hne2(MH,0), MH2 = MH*MH, PS = MH+Mb, MS = MH-Mb
// accN = Mb.Mb^T                  accG = MH.MH^T
// accP = PS.MS^T             =>   s1 = G - n - P
// accQ = MH2.Mb^T + Mb.MH2^T =>   s2 = Q - 2G
extern __shared__ char dynsmem[];

__global__ __launch_bounds__(128, 2)
void gemm_kernel() {
    // exact triangular cover: grid (NTILE+1, NTILE/2); rows y and NTILE-1-y
    // have lengths (NTILE-y)+(y+1) = NTILE+1, packed into one grid row.
    int bi, bj;
    {
        int x = blockIdx.x, y = blockIdx.y;
        int len0 = NTILE - y;
        if (x < len0) { bi = y;             bj = y + x; }
        else          { bi = NTILE - 1 - y; bj = bi + (x - len0); }
    }

    const int tid  = threadIdx.x;
    const int lane = tid & 31;
    const int warp = tid >> 5;                  // 0..3
    const int wm = warp >> 1;                   // 0..1 -> 32-row slab
    const int wn = warp & 1;                    // 0..1 -> 32-col slab
    const int g  = lane >> 2;
    const int tg = lane & 3;
    const int ib = bi * BM, jb = bj * BN;

    unsigned raw = (unsigned)__cvta_generic_to_shared(dynsmem);
    unsigned sb0 = (raw + 1023u) & ~1023u;      // 1024-aligned stage area
    char* auxg = dynsmem + (sb0 - raw);
    unsigned long long* keyI = (unsigned long long*)(auxg + KEYI_OFF);
    unsigned long long* keyJ = (unsigned long long*)(auxg + KEYJ_OFF);
    int* s_amJ = (int*)(auxg + AMJ_OFF);

    if (tid < BM)            keyI[tid] = ~0ull;
    else {                   keyJ[tid - BM] = ~0ull; s_amJ[tid - BM] = g_am[jb + tid - BM]; }

    float accN[2][4][4], accG[2][4][4], accP[2][4][4], accQ[2][4][4];
    #pragma unroll
    for (int a = 0; a < 2; a++)
        #pragma unroll
        for (int b = 0; b < 4; b++)
            #pragma unroll
            for (int c = 0; c < 4; c++) {
                accN[a][b][c] = 0.f; accG[a][b][c] = 0.f;
                accP[a][b][c] = 0.f; accQ[a][b][c] = 0.f;
            }

    // ---- stage loader: 2 MH tiles (A rows=ib, B rows=jb) x 64 rows x 16 chunks
    auto load_stage = [&](int stage, int kt) {
        unsigned sb = sb0 + stage * STAGE_BYTES;
        int kcol = kt * BK;
        #pragma unroll
        for (int it = 0; it < 16; it++) {          // 2*64*16 = 2048 chunks / 128 thr
            int id = tid + it * 128;
            int op = id >> 10;                     // 0..1
            int rem = id & 1023, r = rem >> 4, c = rem & 15;
            int rowbase = op ? jb : ib;
            const __nv_bfloat16* gp = g_MH + (size_t)(rowbase + r) * D_DIM + kcol + c * 8;
            cp_async16(sb + op * OP_BYTES + r * 256 + swz(c, r), gp);
        }
    };

    // ldmatrix per-lane geometry
    const int a_lrow = lane & 15;
    const int a_half = lane >> 4;
    const int b_lrow = (lane & 7) + ((lane >> 4) << 3);
    const int b_half = (lane >> 3) & 1;

    load_stage(0, 0); cp_commit();
    load_stage(1, 1); cp_commit();

    #pragma unroll 1
    for (int kt = 0; kt < NT; kt++) {
        if (kt < NT - 1) cp_wait1(); else cp_wait0();   // stage kt resident
        __syncthreads();                                 // kt-1 consumption done
        if (kt + 2 < NT) { load_stage((kt + 2) % NSTAGE, kt + 2); cp_commit(); }

        unsigned sb = sb0 + (kt % NSTAGE) * STAGE_BYTES;
        #pragma unroll
        for (int kk8 = 0; kk8 < 16; kk8 += 2) {      // 8 k-chunks of 16
            // ---- all 4 ldsm issued back-to-back (MLP=4 on smem loads) ------
            unsigned br0[4], br1[4], aMH0[4], aMH1[4];
            {
                int row0 = wn * 32 + b_lrow;
                int row1 = wn * 32 + 16 + b_lrow;
                ldsm_x4(br0, sb + B_OFF + row0 * 256 + swz(kk8 + b_half, row0));
                ldsm_x4(br1, sb + B_OFF + row1 * 256 + swz(kk8 + b_half, row1));
                int ar0 = wm * 32 + a_lrow;
                int ar1 = wm * 32 + 16 + a_lrow;
                ldsm_x4(aMH0, sb + ar0 * 256 + swz(kk8 + a_half, ar0));
                ldsm_x4(aMH1, sb + ar1 * 256 + swz(kk8 + a_half, ar1));
            }
            unsigned bMH[4][2];
            bMH[0][0] = br0[0]; bMH[0][1] = br0[1];
            bMH[1][0] = br0[2]; bMH[1][1] = br0[3];
            bMH[2][0] = br1[0]; bMH[2][1] = br1[1];
            bMH[3][0] = br1[2]; bMH[3][1] = br1[3];

            unsigned bMb[4][2], bMH2[4][2], bMS[4][2];
            #pragma unroll
            for (int nf = 0; nf < 4; nf++)
                #pragma unroll
                for (int rr = 0; rr < 2; rr++) {
                    unsigned mh = bMH[nf][rr];
                    unsigned mb = hne2z(mh);
                    bMb[nf][rr]  = mb;
                    bMS[nf][rr]  = hsub2u(mh, mb);
                    bMH2[nf][rr] = hmul2u(mh, mh);
                }
            // A fragments per mf row-slab
            #pragma unroll
            for (int mf = 0; mf < 2; mf++) {
                const unsigned* aMH = mf ? aMH1 : aMH0;
                unsigned aMb[4], aPS[4], aMH2[4];
                #pragma unroll
                for (int q = 0; q < 4; q++) {
                    aMb[q]  = hne2z(aMH[q]);
                    aPS[q]  = hadd2u(aMH[q], aMb[q]);
                    aMH2[q] = hmul2u(aMH[q], aMH[q]);
                }
                #pragma unroll
                for (int nf = 0; nf < 4; nf++) {
                    mma16816(accN[mf][nf], aMb,  bMb[nf]);    // n += Mb.Mb
                    mma16816(accG[mf][nf], aMH,  bMH[nf]);    // G += MH.MH
                    mma16816(accP[mf][nf], aPS,  bMS[nf]);    // P += (MH+Mb).(MH-Mb)
                    mma16816(accQ[mf][nf], aMb,  bMH2[nf]);   // Q += Mb.MH2
                    mma16816(accQ[mf][nf], aMH2, bMb[nf]);    // Q += MH2.Mb
                }
            }
        }
    }

    // ---- epilogue: score + packed (score,index) min-reduction --------------
    unsigned long long rk[2][2] = {{~0ull, ~0ull}, {~0ull, ~0ull}};   // [mf][rr]
    unsigned long long ck[4][2] = {{~0ull,~0ull},{~0ull,~0ull},{~0ull,~0ull},{~0ull,~0ull}};

    #pragma unroll
    for (int mf = 0; mf < 2; mf++) {
        const int i0 = ib + wm * 32 + mf * 16 + g;
        const int am0 = g_am[i0];
        const int am1 = g_am[i0 + 8];
        #pragma unroll
        for (int nf = 0; nf < 4; nf++)
            #pragma unroll
            for (int idx = 0; idx < 4; idx++) {
                int rr = idx >> 1, c = idx & 1;
                int i = i0 + rr * 8;
                int jl = wn * 32 + nf * 8 + tg * 2 + c;
                int j = jb + jl;
                float nn = accN[mf][nf][idx];
                int ami = rr ? am1 : am0;
                if (i != j && nn > 1.5f && ami != s_amJ[jl]) {
                    float ns = fmaxf(nn, 2.f);
                    float gg = accG[mf][nf][idx];
                    float s1 = gg - nn - accP[mf][nf][idx];
                    float s2 = accQ[mf][nf][idx] - 2.f * gg;
                    float var = (s2 - s1 * s1 / ns) / (ns - 1.f);
                    rk[mf][rr] = ullmin2(rk[mf][rr], pack_key(var, j));
                    ck[nf][c]  = ullmin2(ck[nf][c],  pack_key(var, i));
                }
            }
    }

    // row-side: min over quad lanes (same row, different cols)
    #pragma unroll
    for (int mf = 0; mf < 2; mf++)
        #pragma unroll
        for (int rr = 0; rr < 2; rr++) {
            unsigned long long v = rk[mf][rr];
            v = ullmin2(v, __shfl_xor_sync(0xffffffffu, v, 1));
            v = ullmin2(v, __shfl_xor_sync(0xffffffffu, v, 2));
            if (tg == 0 && v != ~0ull)
                atomicMin(&keyI[wm * 32 + mf * 16 + rr * 8 + g], v);
        }
    // col-side: min over lanes sharing tg (same cols, different rows)
    #pragma unroll
    for (int nf = 0; nf < 4; nf++)
        #pragma unroll
        for (int c = 0; c < 2; c++) {
            unsigned long long v = ck[nf][c];
            v = ullmin2(v, __shfl_down_sync(0xffffffffu, v, 4));
            v = ullmin2(v, __shfl_down_sync(0xffffffffu, v, 8));
            v = ullmin2(v, __shfl_down_sync(0xffffffffu, v, 16));
            if (g == 0 && v != ~0ull)
                atomicMin(&keyJ[wn * 32 + nf * 8 + tg * 2 + c], v);
        }

    __syncthreads();
    if (tid < BM) {
        if (keyI[tid] != ~0ull) atomicMin(&g_rowmin[ib + tid], keyI[tid]);
    } else {
        if (keyJ[tid - BM] != ~0ull) atomicMin(&g_rowmin[jb + tid - BM], keyJ[tid - BM]);
    }
}

// ---------------- kernel 3: row loss, warp-per-row ---------------------------
__global__ void rowloss_kernel(const float* __restrict__ H) {
    int warp = threadIdx.x >> 5;                   // 4 warps/block
    int lane = threadIdx.x & 31;
    int i = blockIdx.x * 4 + warp;
    int j = (int)(g_rowmin[i] & 0xFFFFFFFFull);
    const float* ri = H + (size_t)i * D_DIM;
    const float* rj = H + (size_t)j * D_DIM;
    float s = 0.f;
    #pragma unroll
    for (int it = 0; it < 8; it++) {               // 8 x 32 lanes x float4 = 1024
        float4 va = *(const float4*)(ri + it * 128 + lane * 4);
        float4 vb = *(const float4*)(rj + it * 128 + lane * 4);
        float dx = va.x - vb.x, dy = va.y - vb.y, dz = va.z - vb.z, dw = va.w - vb.w;
        s += dx * dx + dy * dy + dz * dz + dw * dw;
    }
    #pragma unroll
    for (int off = 16; off > 0; off >>= 1)
        s += __shfl_xor_sync(0xffffffffu, s, off);
    if (lane == 0) g_rowlossp[i] = sqrt((double)s);
}

// ---------------- kernel 4: combine (1024 threads, MLP=8/thread) ------------
__global__ void final_kernel(float* out) {
    int t = threadIdx.x;                           // 1024 threads
    int lane = t & 31, wid = t >> 5;               // 32 warps
    double sm = 0.0, sr = 0.0;
    #pragma unroll
    for (int q = 0; q < 4; q++) {                  // 8 independent loads in flight
        int k = t + q * 1024;
        sm += g_msep[k];
        sr += g_rowlossp[k];
    }
    #pragma unroll
    for (int off = 16; off > 0; off >>= 1) {
        sm += __shfl_xor_sync(0xffffffffu, sm, off);
        sr += __shfl_xor_sync(0xffffffffu, sr, off);
    }
    __shared__ double shm[32], shr[32];
    if (lane == 0) { shm[wid] = sm; shr[wid] = sr; }
    __syncthreads();
    if (wid == 0) {
        sm = shm[lane]; sr = shr[lane];
        #pragma unroll
        for (int off = 16; off > 0; off >>= 1) {
            sm += __shfl_xor_sync(0xffffffffu, sm, off);
            sr += __shfl_xor_sync(0xffffffffu, sr, off);
        }
        if (lane == 0) out[0] = (float)(sm + 10.0 * sr);
    }
}

// ---------------- launch ------------------------------------------------------
extern "C" void kernel_launch(void* const* d_in, const int* in_sizes, int n_in,
                              void* d_out, int out_size) {
    const float* X = (const float*)d_in[0];
    const float* H = (const float*)d_in[1];
    const float* C = (const float*)d_in[2];
    const float* M = (const float*)d_in[3];
    (void)in_sizes; (void)n_in; (void)out_size;

    cudaFuncSetAttribute(gemm_kernel, cudaFuncAttributeMaxDynamicSharedMemorySize, SMEM_REQ);

    prep_kernel<<<T_DIM, 256>>>(X, H, C, M);
    dim3 grid(NTILE + 1, NTILE / 2);               // (65, 32) exact triangle cover
    gemm_kernel<<<grid, 128, SMEM_REQ>>>();
    rowloss_kernel<<<T_DIM / 4, 128>>>(H);
    final_kernel<<<1, 1024>>>((float*)d_out);
}

// round 12
// speedup vs baseline: 1.0092x; 1.0045x over previous
#include <cuda_runtime.h>
#include <cuda_bf16.h>
#include <math.h>
#include <stdint.h>

// Problem constants (fixed shapes per reference)
#define T_DIM 4096
#define D_DIM 1024
#define BM    64
#define BN    64
#define BK    128                   // bf16 elems per k-tile (256B per row)
#define NT    (D_DIM / BK)          // 8 k-tiles
#define NTILE (T_DIM / BM)          // 64

#define OP_BYTES   (64 * 256)       // one MH tile: 64 rows x 256B
#define B_OFF      OP_BYTES
#define STAGE_BYTES (2 * OP_BYTES)  // 32768 (A-MH + B-MH)
#define NSTAGE 3

#define AUX_OFF   (NSTAGE * STAGE_BYTES)    // 98304
#define KEYI_OFF  (AUX_OFF)                 // 64*8 = 512
#define KEYJ_OFF  (AUX_OFF + 512)           // 64*8 = 512
#define AMJ_OFF   (AUX_OFF + 1024)          // 64*4 = 256
#define AUX_BYTES 1280
#define SMEM_REQ  (AUX_OFF + AUX_BYTES + 1008)

#define RL_BLOCKS (T_DIM / 4)               // 1024 rowloss blocks (4 rows each)

// ---------------- scratch (static device allocations; no cudaMalloc) -------
__device__ __nv_bfloat16 g_MH [T_DIM * D_DIM];
__device__ int                g_am[T_DIM];
__device__ unsigned long long g_rowmin[T_DIM];
__device__ float              g_msep[T_DIM];      // per-row mse partials
__device__ float              g_rowlossp[T_DIM];  // per-row norm partials
__device__ unsigned           g_done = 0;         // last-block counter (self-resetting)

// ---------------- helpers ---------------------------------------------------
__device__ __forceinline__ unsigned long long pack_key(float s, int idx) {
    unsigned int u = __float_as_uint(s);
    u = (u & 0x80000000u) ? ~u : (u | 0x80000000u);   // order-preserving float->uint
    return ((unsigned long long)u << 32) | (unsigned int)idx;
}
__device__ __forceinline__ unsigned long long ullmin2(unsigned long long a, unsigned long long b) {
    return a < b ? a : b;
}
__device__ __forceinline__ void mma16816(float* c, const unsigned* a, const unsigned* b) {
    asm volatile(
        "mma.sync.aligned.m16n8k16.row.col.f32.bf16.bf16.f32 "
        "{%0,%1,%2,%3}, {%4,%5,%6,%7}, {%8,%9}, {%0,%1,%2,%3};"
        : "+f"(c[0]), "+f"(c[1]), "+f"(c[2]), "+f"(c[3])
        : "r"(a[0]), "r"(a[1]), "r"(a[2]), "r"(a[3]), "r"(b[0]), "r"(b[1]));
}
__device__ __forceinline__ void ldsm_x4(unsigned* r, unsigned addr) {
    asm volatile("ldmatrix.sync.aligned.m8n8.x4.shared.b16 {%0,%1,%2,%3}, [%4];"
        : "=r"(r[0]), "=r"(r[1]), "=r"(r[2]), "=r"(r[3]) : "r"(addr));
}
__device__ __forceinline__ void cp_async16(unsigned saddr, const void* gaddr) {
    asm volatile("cp.async.cg.shared.global [%0], [%1], 16;" :: "r"(saddr), "l"(gaddr));
}
__device__ __forceinline__ void cp_commit() { asm volatile("cp.async.commit_group;"); }
__device__ __forceinline__ void cp_wait1()  { asm volatile("cp.async.wait_group 1;"); }
__device__ __forceinline__ void cp_wait0()  { asm volatile("cp.async.wait_group 0;"); }

__device__ __forceinline__ unsigned hne2z(unsigned a) {        // 1.0 where != 0
    __nv_bfloat162 va = *reinterpret_cast<__nv_bfloat162*>(&a);
    __nv_bfloat162 z; *reinterpret_cast<unsigned*>(&z) = 0u;
    __nv_bfloat162 r = __hne2(va, z);
    return *reinterpret_cast<unsigned*>(&r);
}
__device__ __forceinline__ unsigned hadd2u(unsigned a, unsigned b) {
    __nv_bfloat162 va = *reinterpret_cast<__nv_bfloat162*>(&a);
    __nv_bfloat162 vb = *reinterpret_cast<__nv_bfloat162*>(&b);
    __nv_bfloat162 r = __hadd2(va, vb);
    return *reinterpret_cast<unsigned*>(&r);
}
__device__ __forceinline__ unsigned hsub2u(unsigned a, unsigned b) {
    __nv_bfloat162 va = *reinterpret_cast<__nv_bfloat162*>(&a);
    __nv_bfloat162 vb = *reinterpret_cast<__nv_bfloat162*>(&b);
    __nv_bfloat162 r = __hsub2(va, vb);
    return *reinterpret_cast<unsigned*>(&r);
}
__device__ __forceinline__ unsigned hmul2u(unsigned a, unsigned b) {
    __nv_bfloat162 va = *reinterpret_cast<__nv_bfloat162*>(&a);
    __nv_bfloat162 vb = *reinterpret_cast<__nv_bfloat162*>(&b);
    __nv_bfloat162 r = __hmul2(va, vb);
    return *reinterpret_cast<unsigned*>(&r);
}

// swizzled byte offset within one 64x256B tile (chunk c in 0..15, row r)
__device__ __forceinline__ unsigned swz(int c, int r) {
    return (((unsigned)((c & 7) ^ (r & 7))) << 4) + ((unsigned)(c >> 3) << 7);
}

// ---------------- kernel 1: build bf16 MH, am[], row-min init, mse partial --
__global__ void prep_kernel(const float* __restrict__ X, const float* __restrict__ H,
                            const float* __restrict__ C, const float* __restrict__ M) {
    int i = blockIdx.x;
    int t = threadIdx.x;                       // 256 threads, 4 elems each
    const size_t base = (size_t)i * D_DIM;
    float4 m4 = *(const float4*)(M + base + t * 4);
    float4 h4 = *(const float4*)(H + base + t * 4);
    float4 x4 = *(const float4*)(X + base + t * 4);
    float4 c4 = *(const float4*)(C + base + t * 4);

    float mv[4] = {m4.x, m4.y, m4.z, m4.w};
    float hv[4] = {h4.x, h4.y, h4.z, h4.w};
    float xv[4] = {x4.x, x4.y, x4.z, x4.w};
    float cv[4] = {c4.x, c4.y, c4.z, c4.w};

    __nv_bfloat16 oh[4];
    float bestv = 3.4e38f; int besti = 0;
    float msum = 0.f;
    #pragma unroll
    for (int q = 0; q < 4; q++) {
        float mb = (mv[q] > 0.f) ? 1.f : 0.f;
        oh[q] = __float2bfloat16(mb * hv[q]);
        float e = (xv[q] - (hv[q] - cv[q])) * mv[q];
        msum += e * e;
        if (mv[q] < bestv) { bestv = mv[q]; besti = t * 4 + q; }
    }
    *(uint2*)(g_MH + base + t * 4) = *(uint2*)oh;

    __shared__ float sv[256]; __shared__ int si[256]; __shared__ float ss[256];
    sv[t] = bestv; si[t] = besti; ss[t] = msum;
    __syncthreads();
    for (int o = 128; o > 0; o >>= 1) {
        if (t < o) {
            if (sv[t + o] < sv[t] || (sv[t + o] == sv[t] && si[t + o] < si[t])) {
                sv[t] = sv[t + o]; si[t] = si[t + o];
            }
            ss[t] += ss[t + o];
        }
        __syncthreads();
    }
    if (t == 0) {
        g_am[i] = si[0];
        g_msep[i] = ss[0];
        g_rowmin[i] = pack_key(9999.0f, 0);    // sentinel for argmin kernel
    }
}

// ---------------- kernel 2: MH-only fused GEMM + score argmin ---------------
// All operands derived from MH in registers:
//   Mb = hne2(MH,0), MH2 = MH*MH, PS = MH+Mb, MS = MH-Mb
// accN = Mb.Mb^T                  accG = MH.MH^T
// accP = PS.MS^T             =>   s1 = G - n - P
// accQ = MH2.Mb^T + Mb.MH2^T =>   s2 = Q - 2G
extern __shared__ char dynsmem[];

__global__ __launch_bounds__(128, 2)
void gemm_kernel() {
    // exact triangular cover: grid (NTILE+1, NTILE/2); rows y and NTILE-1-y
    // have lengths (NTILE-y)+(y+1) = NTILE+1, packed into one grid row.
    int bi, bj;
    {
        int x = blockIdx.x, y = blockIdx.y;
        int len0 = NTILE - y;
        if (x < len0) { bi = y;             bj = y + x; }
        else          { bi = NTILE - 1 - y; bj = bi + (x - len0); }
    }

    const int tid  = threadIdx.x;
    const int lane = tid & 31;
    const int warp = tid >> 5;                  // 0..3
    const int wm = warp >> 1;                   // 0..1 -> 32-row slab
    const int wn = warp & 1;                    // 0..1 -> 32-col slab
    const int g  = lane >> 2;
    const int tg = lane & 3;
    const int ib = bi * BM, jb = bj * BN;

    unsigned raw = (unsigned)__cvta_generic_to_shared(dynsmem);
    unsigned sb0 = (raw + 1023u) & ~1023u;      // 1024-aligned stage area
    char* auxg = dynsmem + (sb0 - raw);
    unsigned long long* keyI = (unsigned long long*)(auxg + KEYI_OFF);
    unsigned long long* keyJ = (unsigned long long*)(auxg + KEYJ_OFF);
    int* s_amJ = (int*)(auxg + AMJ_OFF);

    if (tid < BM)            keyI[tid] = ~0ull;
    else {                   keyJ[tid - BM] = ~0ull; s_amJ[tid - BM] = g_am[jb + tid - BM]; }

    float accN[2][4][4], accG[2][4][4], accP[2][4][4], accQ[2][4][4];
    #pragma unroll
    for (int a = 0; a < 2; a++)
        #pragma unroll
        for (int b = 0; b < 4; b++)
            #pragma unroll
            for (int c = 0; c < 4; c++) {
                accN[a][b][c] = 0.f; accG[a][b][c] = 0.f;
                accP[a][b][c] = 0.f; accQ[a][b][c] = 0.f;
            }

    // ---- stage loader: 2 MH tiles (A rows=ib, B rows=jb) x 64 rows x 16 chunks
    auto load_stage = [&](int stage, int kt) {
        unsigned sb = sb0 + stage * STAGE_BYTES;
        int kcol = kt * BK;
        #pragma unroll
        for (int it = 0; it < 16; it++) {          // 2*64*16 = 2048 chunks / 128 thr
            int id = tid + it * 128;
            int op = id >> 10;                     // 0..1
            int rem = id & 1023, r = rem >> 4, c = rem & 15;
            int rowbase = op ? jb : ib;
            const __nv_bfloat16* gp = g_MH + (size_t)(rowbase + r) * D_DIM + kcol + c * 8;
            cp_async16(sb + op * OP_BYTES + r * 256 + swz(c, r), gp);
        }
    };

    // ldmatrix per-lane geometry
    const int a_lrow = lane & 15;
    const int a_half = lane >> 4;
    const int b_lrow = (lane & 7) + ((lane >> 4) << 3);
    const int b_half = (lane >> 3) & 1;

    load_stage(0, 0); cp_commit();
    load_stage(1, 1); cp_commit();

    #pragma unroll 1
    for (int kt = 0; kt < NT; kt++) {
        if (kt < NT - 1) cp_wait1(); else cp_wait0();   // stage kt resident
        __syncthreads();                                 // kt-1 consumption done
        if (kt + 2 < NT) { load_stage((kt + 2) % NSTAGE, kt + 2); cp_commit(); }

        unsigned sb = sb0 + (kt % NSTAGE) * STAGE_BYTES;
        #pragma unroll
        for (int kk8 = 0; kk8 < 16; kk8 += 2) {      // 8 k-chunks of 16
            // ---- all 4 ldsm issued back-to-back (MLP=4 on smem loads) ------
            unsigned br0[4], br1[4], aMH0[4], aMH1[4];
            {
                int row0 = wn * 32 + b_lrow;
                int row1 = wn * 32 + 16 + b_lrow;
                ldsm_x4(br0, sb + B_OFF + row0 * 256 + swz(kk8 + b_half, row0));
                ldsm_x4(br1, sb + B_OFF + row1 * 256 + swz(kk8 + b_half, row1));
                int ar0 = wm * 32 + a_lrow;
                int ar1 = wm * 32 + 16 + a_lrow;
                ldsm_x4(aMH0, sb + ar0 * 256 + swz(kk8 + a_half, ar0));
                ldsm_x4(aMH1, sb + ar1 * 256 + swz(kk8 + a_half, ar1));
            }
            unsigned bMH[4][2];
            bMH[0][0] = br0[0]; bMH[0][1] = br0[1];
            bMH[1][0] = br0[2]; bMH[1][1] = br0[3];
            bMH[2][0] = br1[0]; bMH[2][1] = br1[1];
            bMH[3][0] = br1[2]; bMH[3][1] = br1[3];

            unsigned bMb[4][2], bMH2[4][2], bMS[4][2];
            #pragma unroll
            for (int nf = 0; nf < 4; nf++)
                #pragma unroll
                for (int rr = 0; rr < 2; rr++) {
                    unsigned mh = bMH[nf][rr];
                    unsigned mb = hne2z(mh);
                    bMb[nf][rr]  = mb;
                    bMS[nf][rr]  = hsub2u(mh, mb);
                    bMH2[nf][rr] = hmul2u(mh, mh);
                }
            // A fragments per mf row-slab
            #pragma unroll
            for (int mf = 0; mf < 2; mf++) {
                const unsigned* aMH = mf ? aMH1 : aMH0;
                unsigned aMb[4], aPS[4], aMH2[4];
                #pragma unroll
                for (int q = 0; q < 4; q++) {
                    aMb[q]  = hne2z(aMH[q]);
                    aPS[q]  = hadd2u(aMH[q], aMb[q]);
                    aMH2[q] = hmul2u(aMH[q], aMH[q]);
                }
                #pragma unroll
                for (int nf = 0; nf < 4; nf++) {
                    mma16816(accN[mf][nf], aMb,  bMb[nf]);    // n += Mb.Mb
                    mma16816(accG[mf][nf], aMH,  bMH[nf]);    // G += MH.MH
                    mma16816(accP[mf][nf], aPS,  bMS[nf]);    // P += (MH+Mb).(MH-Mb)
                    mma16816(accQ[mf][nf], aMb,  bMH2[nf]);   // Q += Mb.MH2
                    mma16816(accQ[mf][nf], aMH2, bMb[nf]);    // Q += MH2.Mb
                }
            }
        }
    }

    // ---- epilogue: score + packed (score,index) min-reduction --------------
    unsigned long long rk[2][2] = {{~0ull, ~0ull}, {~0ull, ~0ull}};   // [mf][rr]
    unsigned long long ck[4][2] = {{~0ull,~0ull},{~0ull,~0ull},{~0ull,~0ull},{~0ull,~0ull}};

    #pragma unroll
    for (int mf = 0; mf < 2; mf++) {
        const int i0 = ib + wm * 32 + mf * 16 + g;
        const int am0 = g_am[i0];
        const int am1 = g_am[i0 + 8];
        #pragma unroll
        for (int nf = 0; nf < 4; nf++)
            #pragma unroll
            for (int idx = 0; idx < 4; idx++) {
                int rr = idx >> 1, c = idx & 1;
                int i = i0 + rr * 8;
                int jl = wn * 32 + nf * 8 + tg * 2 + c;
                int j = jb + jl;
                float nn = accN[mf][nf][idx];
                int ami = rr ? am1 : am0;
                if (i != j && nn > 1.5f && ami != s_amJ[jl]) {
                    float ns = fmaxf(nn, 2.f);
                    float gg = accG[mf][nf][idx];
                    float s1 = gg - nn - accP[mf][nf][idx];
                    float s2 = accQ[mf][nf][idx] - 2.f * gg;
                    float var = (s2 - s1 * s1 / ns) / (ns - 1.f);
                    rk[mf][rr] = ullmin2(rk[mf][rr], pack_key(var, j));
                    ck[nf][c]  = ullmin2(ck[nf][c],  pack_key(var, i));
                }
            }
    }

    // row-side: min over quad lanes (same row, different cols)
    #pragma unroll
    for (int mf = 0; mf < 2; mf++)
        #pragma unroll
        for (int rr = 0; rr < 2; rr++) {
            unsigned long long v = rk[mf][rr];
            v = ullmin2(v, __shfl_xor_sync(0xffffffffu, v, 1));
            v = ullmin2(v, __shfl_xor_sync(0xffffffffu, v, 2));
            if (tg == 0 && v != ~0ull)
                atomicMin(&keyI[wm * 32 + mf * 16 + rr * 8 + g], v);
        }
    // col-side: min over lanes sharing tg (same cols, different rows)
    #pragma unroll
    for (int nf = 0; nf < 4; nf++)
        #pragma unroll
        for (int c = 0; c < 2; c++) {
            unsigned long long v = ck[nf][c];
            v = ullmin2(v, __shfl_down_sync(0xffffffffu, v, 4));
            v = ullmin2(v, __shfl_down_sync(0xffffffffu, v, 8));
            v = ullmin2(v, __shfl_down_sync(0xffffffffu, v, 16));
            if (g == 0 && v != ~0ull)
                atomicMin(&keyJ[wn * 32 + nf * 8 + tg * 2 + c], v);
        }

    __syncthreads();
    if (tid < BM) {
        if (keyI[tid] != ~0ull) atomicMin(&g_rowmin[ib + tid], keyI[tid]);
    } else {
        if (keyJ[tid - BM] != ~0ull) atomicMin(&g_rowmin[jb + tid - BM], keyJ[tid - BM]);
    }
}

// ---------------- kernel 3: row loss + last-block final combine -------------
__global__ void rowloss_kernel(const float* __restrict__ H, float* __restrict__ out) {
    int warp = threadIdx.x >> 5;                   // 4 warps/block
    int lane = threadIdx.x & 31;
    int t = threadIdx.x;
    int i = blockIdx.x * 4 + warp;
    int j = (int)(g_rowmin[i] & 0xFFFFFFFFull);
    const float* ri = H + (size_t)i * D_DIM;
    const float* rj = H + (size_t)j * D_DIM;
    float s = 0.f;
    #pragma unroll
    for (int it = 0; it < 8; it++) {               // 8 x 32 lanes x float4 = 1024
        float4 va = *(const float4*)(ri + it * 128 + lane * 4);
        float4 vb = *(const float4*)(rj + it * 128 + lane * 4);
        float dx = va.x - vb.x, dy = va.y - vb.y, dz = va.z - vb.z, dw = va.w - vb.w;
        s += dx * dx + dy * dy + dz * dz + dw * dw;
    }
    #pragma unroll
    for (int off = 16; off > 0; off >>= 1)
        s += __shfl_xor_sync(0xffffffffu, s, off);
    if (lane == 0) g_rowlossp[i] = (float)sqrt((double)s);

    // ---- last block performs the final combine -----------------------------
    __shared__ unsigned s_last;
    __syncthreads();
    if (t == 0) {
        __threadfence();                           // partials visible chip-wide
        unsigned old = atomicAdd(&g_done, 1u);
        s_last = (old == RL_BLOCKS - 1) ? 1u : 0u;
    }
    __syncthreads();
    if (s_last) {
        double sm = 0.0, sr = 0.0;
        #pragma unroll
        for (int q = 0; q < T_DIM / 128; q++) {    // 32 elems per thread, coalesced
            int k = t + q * 128;
            sm += (double)g_msep[k];
            sr += (double)g_rowlossp[k];
        }
        #pragma unroll
        for (int off = 16; off > 0; off >>= 1) {
            sm += __shfl_xor_sync(0xffffffffu, sm, off);
            sr += __shfl_xor_sync(0xffffffffu, sr, off);
        }
        __shared__ double shm[4], shr[4];
        if (lane == 0) { shm[warp] = sm; shr[warp] = sr; }
        __syncthreads();
        if (t == 0) {
            double tm = shm[0] + shm[1] + shm[2] + shm[3];
            double tr = shr[0] + shr[1] + shr[2] + shr[3];
            out[0] = (float)(tm + 10.0 * tr);
            g_done = 0;                            // reset for next graph replay
        }
    }
}

// ---------------- launch ------------------------------------------------------
extern "C" void kernel_launch(void* const* d_in, const int* in_sizes, int n_in,
                              void* d_out, int out_size) {
    const float* X = (const float*)d_in[0];
    const float* H = (const float*)d_in[1];
    const float* C = (const float*)d_in[2];
    const float* M = (const float*)d_in[3];
    (void)in_sizes; (void)n_in; (void)out_size;

    cudaFuncSetAttribute(gemm_kernel, cudaFuncAttributeMaxDynamicSharedMemorySize, SMEM_REQ);

    prep_kernel<<<T_DIM, 256>>>(X, H, C, M);
    dim3 grid(NTILE + 1, NTILE / 2);               // (65, 32) exact triangle cover
    gemm_kernel<<<grid, 128, SMEM_REQ>>>();
    rowloss_kernel<<<RL_BLOCKS, 128>>>(H, (float*)d_out);
}

// round 13
// speedup vs baseline: 1.0162x; 1.0069x over previous
#include <cuda_runtime.h>
#include <cuda_bf16.h>
#include <math.h>
#include <stdint.h>

// Problem constants (fixed shapes per reference)
#define T_DIM 4096
#define D_DIM 1024
#define BM    64
#define BN    64
#define BK    128                   // bf16 elems per k-tile (256B per row)
#define NT    (D_DIM / BK)          // 8 k-tiles
#define NTILE (T_DIM / BM)          // 64

#define OP_BYTES   (64 * 256)       // one MH tile: 64 rows x 256B
#define B_OFF      OP_BYTES
#define STAGE_BYTES (2 * OP_BYTES)  // 32768 (A-MH + B-MH)
#define NSTAGE 3

#define AUX_OFF   (NSTAGE * STAGE_BYTES)    // 98304
#define KEYI_OFF  (AUX_OFF)                 // 64*8 = 512
#define KEYJ_OFF  (AUX_OFF + 512)           // 64*8 = 512
#define AMJ_OFF   (AUX_OFF + 1024)          // 64*4 = 256
#define AUX_BYTES 1280
#define SMEM_REQ  (AUX_OFF + AUX_BYTES + 1008)

#define RL_BLOCKS (T_DIM / 4)               // 1024 rowloss blocks (4 rows each)

// ---------------- scratch (static device allocations; no cudaMalloc) -------
__device__ __nv_bfloat16 g_MH [T_DIM * D_DIM];
__device__ int                g_am[T_DIM];
__device__ unsigned long long g_rowmin[T_DIM];
__device__ float              g_msep[T_DIM];      // per-row mse partials
__device__ float              g_rowlossp[T_DIM];  // per-row norm partials
__device__ unsigned           g_done = 0;         // last-block counter (self-resetting)

// ---------------- helpers ---------------------------------------------------
__device__ __forceinline__ unsigned long long pack_key(float s, int idx) {
    unsigned int u = __float_as_uint(s);
    u = (u & 0x80000000u) ? ~u : (u | 0x80000000u);   // order-preserving float->uint
    return ((unsigned long long)u << 32) | (unsigned int)idx;
}
__device__ __forceinline__ unsigned long long ullmin2(unsigned long long a, unsigned long long b) {
    return a < b ? a : b;
}
__device__ __forceinline__ void mma16816(float* c, const unsigned* a, const unsigned* b) {
    asm volatile(
        "mma.sync.aligned.m16n8k16.row.col.f32.bf16.bf16.f32 "
        "{%0,%1,%2,%3}, {%4,%5,%6,%7}, {%8,%9}, {%0,%1,%2,%3};"
        : "+f"(c[0]), "+f"(c[1]), "+f"(c[2]), "+f"(c[3])
        : "r"(a[0]), "r"(a[1]), "r"(a[2]), "r"(a[3]), "r"(b[0]), "r"(b[1]));
}
__device__ __forceinline__ void ldsm_x4(unsigned* r, unsigned addr) {
    asm volatile("ldmatrix.sync.aligned.m8n8.x4.shared.b16 {%0,%1,%2,%3}, [%4];"
        : "=r"(r[0]), "=r"(r[1]), "=r"(r[2]), "=r"(r[3]) : "r"(addr));
}
__device__ __forceinline__ void cp_async16(unsigned saddr, const void* gaddr) {
    asm volatile("cp.async.cg.shared.global [%0], [%1], 16;" :: "r"(saddr), "l"(gaddr));
}
__device__ __forceinline__ void cp_commit() { asm volatile("cp.async.commit_group;"); }
__device__ __forceinline__ void cp_wait1()  { asm volatile("cp.async.wait_group 1;"); }
__device__ __forceinline__ void cp_wait0()  { asm volatile("cp.async.wait_group 0;"); }

__device__ __forceinline__ unsigned hne2z(unsigned a) {        // 1.0 where != 0
    __nv_bfloat162 va = *reinterpret_cast<__nv_bfloat162*>(&a);
    __nv_bfloat162 z; *reinterpret_cast<unsigned*>(&z) = 0u;
    __nv_bfloat162 r = __hne2(va, z);
    return *reinterpret_cast<unsigned*>(&r);
}
__device__ __forceinline__ unsigned hadd2u(unsigned a, unsigned b) {
    __nv_bfloat162 va = *reinterpret_cast<__nv_bfloat162*>(&a);
    __nv_bfloat162 vb = *reinterpret_cast<__nv_bfloat162*>(&b);
    __nv_bfloat162 r = __hadd2(va, vb);
    return *reinterpret_cast<unsigned*>(&r);
}
__device__ __forceinline__ unsigned hsub2u(unsigned a, unsigned b) {
    __nv_bfloat162 va = *reinterpret_cast<__nv_bfloat162*>(&a);
    __nv_bfloat162 vb = *reinterpret_cast<__nv_bfloat162*>(&b);
    __nv_bfloat162 r = __hsub2(va, vb);
    return *reinterpret_cast<unsigned*>(&r);
}
__device__ __forceinline__ unsigned hmul2u(unsigned a, unsigned b) {
    __nv_bfloat162 va = *reinterpret_cast<__nv_bfloat162*>(&a);
    __nv_bfloat162 vb = *reinterpret_cast<__nv_bfloat162*>(&b);
    __nv_bfloat162 r = __hmul2(va, vb);
    return *reinterpret_cast<unsigned*>(&r);
}

// swizzled byte offset within one 64x256B tile (chunk c in 0..15, row r)
__device__ __forceinline__ unsigned swz(int c, int r) {
    return (((unsigned)((c & 7) ^ (r & 7))) << 4) + ((unsigned)(c >> 3) << 7);
}

// ---------------- kernel 1: build bf16 MH, am[], row-min init, mse partial --
__global__ void prep_kernel(const float* __restrict__ X, const float* __restrict__ H,
                            const float* __restrict__ C, const float* __restrict__ M) {
    int i = blockIdx.x;
    int t = threadIdx.x;                       // 256 threads, 4 elems each
    const size_t base = (size_t)i * D_DIM;
    float4 m4 = *(const float4*)(M + base + t * 4);
    float4 h4 = *(const float4*)(H + base + t * 4);
    float4 x4 = *(const float4*)(X + base + t * 4);
    float4 c4 = *(const float4*)(C + base + t * 4);

    float mv[4] = {m4.x, m4.y, m4.z, m4.w};
    float hv[4] = {h4.x, h4.y, h4.z, h4.w};
    float xv[4] = {x4.x, x4.y, x4.z, x4.w};
    float cv[4] = {c4.x, c4.y, c4.z, c4.w};

    __nv_bfloat16 oh[4];
    float bestv = 3.4e38f; int besti = 0;
    float msum = 0.f;
    #pragma unroll
    for (int q = 0; q < 4; q++) {
        float mb = (mv[q] > 0.f) ? 1.f : 0.f;
        oh[q] = __float2bfloat16(mb * hv[q]);
        float e = (xv[q] - (hv[q] - cv[q])) * mv[q];
        msum += e * e;
        if (mv[q] < bestv) { bestv = mv[q]; besti = t * 4 + q; }
    }
    *(uint2*)(g_MH + base + t * 4) = *(uint2*)oh;

    __shared__ float sv[256]; __shared__ int si[256]; __shared__ float ss[256];
    sv[t] = bestv; si[t] = besti; ss[t] = msum;
    __syncthreads();
    for (int o = 128; o > 0; o >>= 1) {
        if (t < o) {
            if (sv[t + o] < sv[t] || (sv[t + o] == sv[t] && si[t + o] < si[t])) {
                sv[t] = sv[t + o]; si[t] = si[t + o];
            }
            ss[t] += ss[t + o];
        }
        __syncthreads();
    }
    if (t == 0) {
        g_am[i] = si[0];
        g_msep[i] = ss[0];
        g_rowmin[i] = pack_key(9999.0f, 0);    // sentinel for argmin kernel
    }
}

// ---------------- kernel 2: MH-only fused GEMM + score argmin ---------------
// All operands derived from MH in registers:
//   Mb = hne2(MH,0), MH2 = MH*MH, PS = MH+Mb, MS = MH-Mb
// accN = Mb.Mb^T                  accG = MH.MH^T
// accP = PS.MS^T             =>   s1 = G - n - P
// accQ = MH2.Mb^T + Mb.MH2^T =>   s2 = Q - 2G
extern __shared__ char dynsmem[];

__global__ __launch_bounds__(128, 2)
void gemm_kernel() {
    // exact triangular cover: grid (NTILE+1, NTILE/2); rows y and NTILE-1-y
    // have lengths (NTILE-y)+(y+1) = NTILE+1, packed into one grid row.
    int bi, bj;
    {
        int x = blockIdx.x, y = blockIdx.y;
        int len0 = NTILE - y;
        if (x < len0) { bi = y;             bj = y + x; }
        else          { bi = NTILE - 1 - y; bj = bi + (x - len0); }
    }

    const int tid  = threadIdx.x;
    const int lane = tid & 31;
    const int warp = tid >> 5;                  // 0..3
    const int wm = warp >> 1;                   // 0..1 -> 32-row slab
    const int wn = warp & 1;                    // 0..1 -> 32-col slab
    const int g  = lane >> 2;
    const int tg = lane & 3;
    const int ib = bi * BM, jb = bj * BN;

    unsigned raw = (unsigned)__cvta_generic_to_shared(dynsmem);
    unsigned sb0 = (raw + 1023u) & ~1023u;      // 1024-aligned stage area
    char* auxg = dynsmem + (sb0 - raw);
    unsigned long long* keyI = (unsigned long long*)(auxg + KEYI_OFF);
    unsigned long long* keyJ = (unsigned long long*)(auxg + KEYJ_OFF);
    int* s_amJ = (int*)(auxg + AMJ_OFF);

    if (tid < BM)            keyI[tid] = ~0ull;
    else {                   keyJ[tid - BM] = ~0ull; s_amJ[tid - BM] = g_am[jb + tid - BM]; }

    float accN[2][4][4], accG[2][4][4], accP[2][4][4], accQ[2][4][4];
    #pragma unroll
    for (int a = 0; a < 2; a++)
        #pragma unroll
        for (int b = 0; b < 4; b++)
            #pragma unroll
            for (int c = 0; c < 4; c++) {
                accN[a][b][c] = 0.f; accG[a][b][c] = 0.f;
                accP[a][b][c] = 0.f; accQ[a][b][c] = 0.f;
            }

    // ---- stage loader: 2 MH tiles (A rows=ib, B rows=jb) x 64 rows x 16 chunks
    auto load_stage = [&](int stage, int kt) {
        unsigned sb = sb0 + stage * STAGE_BYTES;
        int kcol = kt * BK;
        #pragma unroll
        for (int it = 0; it < 16; it++) {          // 2*64*16 = 2048 chunks / 128 thr
            int id = tid + it * 128;
            int op = id >> 10;                     // 0..1
            int rem = id & 1023, r = rem >> 4, c = rem & 15;
            int rowbase = op ? jb : ib;
            const __nv_bfloat16* gp = g_MH + (size_t)(rowbase + r) * D_DIM + kcol + c * 8;
            cp_async16(sb + op * OP_BYTES + r * 256 + swz(c, r), gp);
        }
    };

    // ldmatrix per-lane geometry
    const int a_lrow = lane & 15;
    const int a_half = lane >> 4;
    const int b_lrow = (lane & 7) + ((lane >> 4) << 3);
    const int b_half = (lane >> 3) & 1;

    load_stage(0, 0); cp_commit();
    load_stage(1, 1); cp_commit();

    #pragma unroll 1
    for (int kt = 0; kt < NT; kt++) {
        if (kt < NT - 1) cp_wait1(); else cp_wait0();   // stage kt resident
        __syncthreads();                                 // kt-1 consumption done
        if (kt + 2 < NT) { load_stage((kt + 2) % NSTAGE, kt + 2); cp_commit(); }

        unsigned sb = sb0 + (kt % NSTAGE) * STAGE_BYTES;
        #pragma unroll
        for (int kk8 = 0; kk8 < 16; kk8 += 2) {      // 8 k-chunks of 16
            // B fragments: MH + derived Mb, MH2, MS (4 nf x 2 regs each)
            unsigned bMH[4][2], bMb[4][2], bMH2[4][2], bMS[4][2];
            #pragma unroll
            for (int ng = 0; ng < 2; ng++) {
                int row = wn * 32 + ng * 16 + b_lrow;
                unsigned addr = sb + B_OFF + row * 256 + swz(kk8 + b_half, row);
                unsigned r[4]; ldsm_x4(r, addr);
                bMH[2 * ng][0] = r[0]; bMH[2 * ng][1] = r[1];
                bMH[2 * ng + 1][0] = r[2]; bMH[2 * ng + 1][1] = r[3];
            }
            #pragma unroll
            for (int nf = 0; nf < 4; nf++)
                #pragma unroll
                for (int rr = 0; rr < 2; rr++) {
                    unsigned mh = bMH[nf][rr];
                    unsigned mb = hne2z(mh);
                    bMb[nf][rr]  = mb;
                    bMS[nf][rr]  = hsub2u(mh, mb);
                    bMH2[nf][rr] = hmul2u(mh, mh);
                }
            // A fragments per mf row-slab
            #pragma unroll
            for (int mf = 0; mf < 2; mf++) {
                int row = wm * 32 + mf * 16 + a_lrow;
                unsigned arow_off = row * 256 + swz(kk8 + a_half, row);
                unsigned aMH[4]; ldsm_x4(aMH, sb + arow_off);
                unsigned aMb[4], aPS[4], aMH2[4];
                #pragma unroll
                for (int q = 0; q < 4; q++) {
                    aMb[q]  = hne2z(aMH[q]);
                    aPS[q]  = hadd2u(aMH[q], aMb[q]);
                    aMH2[q] = hmul2u(aMH[q], aMH[q]);
                }
                #pragma unroll
                for (int nf = 0; nf < 4; nf++) {
                    mma16816(accN[mf][nf], aMb,  bMb[nf]);    // n += Mb.Mb
                    mma16816(accG[mf][nf], aMH,  bMH[nf]);    // G += MH.MH
                    mma16816(accP[mf][nf], aPS,  bMS[nf]);    // P += (MH+Mb).(MH-Mb)
                    mma16816(accQ[mf][nf], aMb,  bMH2[nf]);   // Q += Mb.MH2
                    mma16816(accQ[mf][nf], aMH2, bMb[nf]);    // Q += MH2.Mb
                }
            }
        }
    }

    // ---- epilogue: score + packed (score,index) min-reduction --------------
    unsigned long long rk[2][2] = {{~0ull, ~0ull}, {~0ull, ~0ull}};   // [mf][rr]
    unsigned long long ck[4][2] = {{~0ull,~0ull},{~0ull,~0ull},{~0ull,~0ull},{~0ull,~0ull}};

    #pragma unroll
    for (int mf = 0; mf < 2; mf++) {
        const int i0 = ib + wm * 32 + mf * 16 + g;
        const int am0 = g_am[i0];
        const int am1 = g_am[i0 + 8];
        #pragma unroll
        for (int nf = 0; nf < 4; nf++)
            #pragma unroll
            for (int idx = 0; idx < 4; idx++) {
                int rr = idx >> 1, c = idx & 1;
                int i = i0 + rr * 8;
                int jl = wn * 32 + nf * 8 + tg * 2 + c;
                int j = jb + jl;
                float nn = accN[mf][nf][idx];
                int ami = rr ? am1 : am0;
                if (i != j && nn > 1.5f && ami != s_amJ[jl]) {
                    float ns = fmaxf(nn, 2.f);
                    float gg = accG[mf][nf][idx];
                    float s1 = gg - nn - accP[mf][nf][idx];
                    float s2 = accQ[mf][nf][idx] - 2.f * gg;
                    float var = (s2 - s1 * s1 / ns) / (ns - 1.f);
                    rk[mf][rr] = ullmin2(rk[mf][rr], pack_key(var, j));
                    ck[nf][c]  = ullmin2(ck[nf][c],  pack_key(var, i));
                }
            }
    }

    // row-side: min over quad lanes (same row, different cols)
    #pragma unroll
    for (int mf = 0; mf < 2; mf++)
        #pragma unroll
        for (int rr = 0; rr < 2; rr++) {
            unsigned long long v = rk[mf][rr];
            v = ullmin2(v, __shfl_xor_sync(0xffffffffu, v, 1));
            v = ullmin2(v, __shfl_xor_sync(0xffffffffu, v, 2));
            if (tg == 0 && v != ~0ull)
                atomicMin(&keyI[wm * 32 + mf * 16 + rr * 8 + g], v);
        }
    // col-side: min over lanes sharing tg (same cols, different rows)
    #pragma unroll
    for (int nf = 0; nf < 4; nf++)
        #pragma unroll
        for (int c = 0; c < 2; c++) {
            unsigned long long v = ck[nf][c];
            v = ullmin2(v, __shfl_down_sync(0xffffffffu, v, 4));
            v = ullmin2(v, __shfl_down_sync(0xffffffffu, v, 8));
            v = ullmin2(v, __shfl_down_sync(0xffffffffu, v, 16));
            if (g == 0 && v != ~0ull)
                atomicMin(&keyJ[wn * 32 + nf * 8 + tg * 2 + c], v);
        }

    __syncthreads();
    if (tid < BM) {
        if (keyI[tid] != ~0ull) atomicMin(&g_rowmin[ib + tid], keyI[tid]);
    } else {
        if (keyJ[tid - BM] != ~0ull) atomicMin(&g_rowmin[jb + tid - BM], keyJ[tid - BM]);
    }
}

// ---------------- kernel 3: row loss + last-block final combine -------------
__global__ void rowloss_kernel(const float* __restrict__ H, float* __restrict__ out) {
    int warp = threadIdx.x >> 5;                   // 4 warps/block
    int lane = threadIdx.x & 31;
    int t = threadIdx.x;
    int i = blockIdx.x * 4 + warp;
    int j = (int)(g_rowmin[i] & 0xFFFFFFFFull);
    const float* ri = H + (size_t)i * D_DIM;
    const float* rj = H + (size_t)j * D_DIM;
    float s = 0.f;
    #pragma unroll
    for (int it = 0; it < 8; it++) {               // 8 x 32 lanes x float4 = 1024
        float4 va = *(const float4*)(ri + it * 128 + lane * 4);
        float4 vb = *(const float4*)(rj + it * 128 + lane * 4);
        float dx = va.x - vb.x, dy = va.y - vb.y, dz = va.z - vb.z, dw = va.w - vb.w;
        s += dx * dx + dy * dy + dz * dz + dw * dw;
    }
    #pragma unroll
    for (int off = 16; off > 0; off >>= 1)
        s += __shfl_xor_sync(0xffffffffu, s, off);
    if (lane == 0) g_rowlossp[i] = (float)sqrt((double)s);

    // ---- last block performs the final combine -----------------------------
    __shared__ unsigned s_last;
    __syncthreads();
    if (t == 0) {
        __threadfence();                           // partials visible chip-wide
        unsigned old = atomicAdd(&g_done, 1u);
        s_last = (old == RL_BLOCKS - 1) ? 1u : 0u;
    }
    __syncthreads();
    if (s_last) {
        double sm = 0.0, sr = 0.0;
        #pragma unroll
        for (int q = 0; q < T_DIM / 128; q++) {    // 32 elems per thread, coalesced
            int k = t + q * 128;
            sm += (double)g_msep[k];
            sr += (double)g_rowlossp[k];
        }
        #pragma unroll
        for (int off = 16; off > 0; off >>= 1) {
            sm += __shfl_xor_sync(0xffffffffu, sm, off);
            sr += __shfl_xor_sync(0xffffffffu, sr, off);
        }
        __shared__ double shm[4], shr[4];
        if (lane == 0) { shm[warp] = sm; shr[warp] = sr; }
        __syncthreads();
        if (t == 0) {
            double tm = shm[0] + shm[1] + shm[2] + shm[3];
            double tr = shr[0] + shr[1] + shr[2] + shr[3];
            out[0] = (float)(tm + 10.0 * tr);
            g_done = 0;                            // reset for next graph replay
        }
    }
}

// ---------------- launch ------------------------------------------------------
extern "C" void kernel_launch(void* const* d_in, const int* in_sizes, int n_in,
                              void* d_out, int out_size) {
    const float* X = (const float*)d_in[0];
    const float* H = (const float*)d_in[1];
    const float* C = (const float*)d_in[2];
    const float* M = (const float*)d_in[3];
    (void)in_sizes; (void)n_in; (void)out_size;

    cudaFuncSetAttribute(gemm_kernel, cudaFuncAttributeMaxDynamicSharedMemorySize, SMEM_REQ);

    prep_kernel<<<T_DIM, 256>>>(X, H, C, M);
    dim3 grid(NTILE + 1, NTILE / 2);               // (65, 32) exact triangle cover
    gemm_kernel<<<grid, 128, SMEM_REQ>>>();
    rowloss_kernel<<<RL_BLOCKS, 128>>>(H, (float*)d_out);
}

// round 14
// speedup vs baseline: 1.0384x; 1.0219x over previous
#include <cuda_runtime.h>
#include <cuda_bf16.h>
#include <math.h>
#include <stdint.h>

// Problem constants (fixed shapes per reference)
#define T_DIM 4096
#define D_DIM 1024
#define BM    64
#define BN    64
#define BK    128                   // bf16 elems per k-tile (256B per row)
#define NT    (D_DIM / BK)          // 8 k-tiles
#define NTILE (T_DIM / BM)          // 64

#define OP_BYTES   (64 * 256)       // one MH tile: 64 rows x 256B
#define B_OFF      OP_BYTES
#define STAGE_BYTES (2 * OP_BYTES)  // 32768 (A-MH + B-MH)
#define NSTAGE 3

#define AUX_OFF   (NSTAGE * STAGE_BYTES)    // 98304
#define KEYI_OFF  (AUX_OFF)                 // 64*8 = 512
#define KEYJ_OFF  (AUX_OFF + 512)           // 64*8 = 512
#define AMJ_OFF   (AUX_OFF + 1024)          // 64*4 = 256
#define AUX_BYTES 1280
#define SMEM_REQ  (AUX_OFF + AUX_BYTES + 1008)

#define RL_BLOCKS (T_DIM / 4)               // 1024 rowloss blocks (4 rows each)

// ---------------- scratch (static device allocations; no cudaMalloc) -------
__device__ __nv_bfloat16 g_MH [T_DIM * D_DIM];
__device__ int                g_am[T_DIM];
__device__ unsigned long long g_rowmin[T_DIM];
__device__ float              g_msep[T_DIM];      // per-row mse partials
__device__ float              g_rowlossp[T_DIM];  // per-row norm partials
__device__ unsigned           g_done = 0;         // last-block counter (self-resetting)

// ---------------- helpers ---------------------------------------------------
__device__ __forceinline__ unsigned long long pack_key(float s, int idx) {
    unsigned int u = __float_as_uint(s);
    u = (u & 0x80000000u) ? ~u : (u | 0x80000000u);   // order-preserving float->uint
    return ((unsigned long long)u << 32) | (unsigned int)idx;
}
__device__ __forceinline__ unsigned long long ullmin2(unsigned long long a, unsigned long long b) {
    return a < b ? a : b;
}
__device__ __forceinline__ void mma16816(float* c, const unsigned* a, const unsigned* b) {
    asm volatile(
        "mma.sync.aligned.m16n8k16.row.col.f32.bf16.bf16.f32 "
        "{%0,%1,%2,%3}, {%4,%5,%6,%7}, {%8,%9}, {%0,%1,%2,%3};"
        : "+f"(c[0]), "+f"(c[1]), "+f"(c[2]), "+f"(c[3])
        : "r"(a[0]), "r"(a[1]), "r"(a[2]), "r"(a[3]), "r"(b[0]), "r"(b[1]));
}
__device__ __forceinline__ void ldsm_x4(unsigned* r, unsigned addr) {
    asm volatile("ldmatrix.sync.aligned.m8n8.x4.shared.b16 {%0,%1,%2,%3}, [%4];"
        : "=r"(r[0]), "=r"(r[1]), "=r"(r[2]), "=r"(r[3]) : "r"(addr));
}
__device__ __forceinline__ void cp_async16(unsigned saddr, const void* gaddr) {
    asm volatile("cp.async.cg.shared.global [%0], [%1], 16;" :: "r"(saddr), "l"(gaddr));
}
__device__ __forceinline__ void cp_commit() { asm volatile("cp.async.commit_group;"); }
__device__ __forceinline__ void cp_wait1()  { asm volatile("cp.async.wait_group 1;"); }
__device__ __forceinline__ void cp_wait0()  { asm volatile("cp.async.wait_group 0;"); }

__device__ __forceinline__ unsigned hne2z(unsigned a) {        // 1.0 where != 0
    __nv_bfloat162 va = *reinterpret_cast<__nv_bfloat162*>(&a);
    __nv_bfloat162 z; *reinterpret_cast<unsigned*>(&z) = 0u;
    __nv_bfloat162 r = __hne2(va, z);
    return *reinterpret_cast<unsigned*>(&r);
}
__device__ __forceinline__ unsigned hadd2u(unsigned a, unsigned b) {
    __nv_bfloat162 va = *reinterpret_cast<__nv_bfloat162*>(&a);
    __nv_bfloat162 vb = *reinterpret_cast<__nv_bfloat162*>(&b);
    __nv_bfloat162 r = __hadd2(va, vb);
    return *reinterpret_cast<unsigned*>(&r);
}
__device__ __forceinline__ unsigned hsub2u(unsigned a, unsigned b) {
    __nv_bfloat162 va = *reinterpret_cast<__nv_bfloat162*>(&a);
    __nv_bfloat162 vb = *reinterpret_cast<__nv_bfloat162*>(&b);
    __nv_bfloat162 r = __hsub2(va, vb);
    return *reinterpret_cast<unsigned*>(&r);
}
__device__ __forceinline__ unsigned hmul2u(unsigned a, unsigned b) {
    __nv_bfloat162 va = *reinterpret_cast<__nv_bfloat162*>(&a);
    __nv_bfloat162 vb = *reinterpret_cast<__nv_bfloat162*>(&b);
    __nv_bfloat162 r = __hmul2(va, vb);
    return *reinterpret_cast<unsigned*>(&r);
}

// swizzled byte offset within one 64x256B tile (chunk c in 0..15, row r)
__device__ __forceinline__ unsigned swz(int c, int r) {
    return (((unsigned)((c & 7) ^ (r & 7))) << 4) + ((unsigned)(c >> 3) << 7);
}

// ---------------- kernel 1: build bf16 MH, am[], row-min init, mse partial --
// warp-shuffle reductions: 1 __syncthreads total.
__global__ void prep_kernel(const float* __restrict__ X, const float* __restrict__ H,
                            const float* __restrict__ C, const float* __restrict__ M) {
    int i = blockIdx.x;
    int t = threadIdx.x;                       // 256 threads, 4 elems each
    int lane = t & 31, wid = t >> 5;           // 8 warps
    const size_t base = (size_t)i * D_DIM;
    float4 m4 = *(const float4*)(M + base + t * 4);
    float4 h4 = *(const float4*)(H + base + t * 4);
    float4 x4 = *(const float4*)(X + base + t * 4);
    float4 c4 = *(const float4*)(C + base + t * 4);

    float mv[4] = {m4.x, m4.y, m4.z, m4.w};
    float hv[4] = {h4.x, h4.y, h4.z, h4.w};
    float xv[4] = {x4.x, x4.y, x4.z, x4.w};
    float cv[4] = {c4.x, c4.y, c4.z, c4.w};

    __nv_bfloat16 oh[4];
    unsigned long long amkey = ~0ull;
    float msum = 0.f;
    #pragma unroll
    for (int q = 0; q < 4; q++) {
        float mb = (mv[q] > 0.f) ? 1.f : 0.f;
        oh[q] = __float2bfloat16(mb * hv[q]);
        float e = (xv[q] - (hv[q] - cv[q])) * mv[q];
        msum += e * e;
        amkey = ullmin2(amkey, pack_key(mv[q], t * 4 + q));   // min value, then min idx
    }
    *(uint2*)(g_MH + base + t * 4) = *(uint2*)oh;

    // warp reduce
    #pragma unroll
    for (int off = 16; off > 0; off >>= 1) {
        amkey = ullmin2(amkey, __shfl_xor_sync(0xffffffffu, amkey, off));
        msum += __shfl_xor_sync(0xffffffffu, msum, off);
    }
    __shared__ unsigned long long sk[8];
    __shared__ float sm[8];
    if (lane == 0) { sk[wid] = amkey; sm[wid] = msum; }
    __syncthreads();
    if (t == 0) {
        unsigned long long k = sk[0];
        float s = sm[0];
        #pragma unroll
        for (int w = 1; w < 8; w++) { k = ullmin2(k, sk[w]); s += sm[w]; }
        g_am[i] = (int)(k & 0xFFFFFFFFull);
        g_msep[i] = s;
        g_rowmin[i] = pack_key(9999.0f, 0);    // sentinel for argmin kernel
    }
}

// ---------------- kernel 2: MH-only fused GEMM + score argmin ---------------
// All operands derived from MH in registers:
//   Mb = hne2(MH,0), MH2 = MH*MH, PS = MH+Mb, MS = MH-Mb
// accN = Mb.Mb^T                  accG = MH.MH^T
// accP = PS.MS^T             =>   s1 = G - n - P
// accQ = MH2.Mb^T + Mb.MH2^T =>   s2 = Q - 2G
extern __shared__ char dynsmem[];

__global__ __launch_bounds__(128, 2)
void gemm_kernel() {
    // exact triangular cover: grid (NTILE+1, NTILE/2); rows y and NTILE-1-y
    // have lengths (NTILE-y)+(y+1) = NTILE+1, packed into one grid row.
    int bi, bj;
    {
        int x = blockIdx.x, y = blockIdx.y;
        int len0 = NTILE - y;
        if (x < len0) { bi = y;             bj = y + x; }
        else          { bi = NTILE - 1 - y; bj = bi + (x - len0); }
    }

    const int tid  = threadIdx.x;
    const int lane = tid & 31;
    const int warp = tid >> 5;                  // 0..3
    const int wm = warp >> 1;                   // 0..1 -> 32-row slab
    const int wn = warp & 1;                    // 0..1 -> 32-col slab
    const int g  = lane >> 2;
    const int tg = lane & 3;
    const int ib = bi * BM, jb = bj * BN;

    unsigned raw = (unsigned)__cvta_generic_to_shared(dynsmem);
    unsigned sb0 = (raw + 1023u) & ~1023u;      // 1024-aligned stage area
    char* auxg = dynsmem + (sb0 - raw);
    unsigned long long* keyI = (unsigned long long*)(auxg + KEYI_OFF);
    unsigned long long* keyJ = (unsigned long long*)(auxg + KEYJ_OFF);
    int* s_amJ = (int*)(auxg + AMJ_OFF);

    if (tid < BM)            keyI[tid] = ~0ull;
    else {                   keyJ[tid - BM] = ~0ull; s_amJ[tid - BM] = g_am[jb + tid - BM]; }

    float accN[2][4][4], accG[2][4][4], accP[2][4][4], accQ[2][4][4];
    #pragma unroll
    for (int a = 0; a < 2; a++)
        #pragma unroll
        for (int b = 0; b < 4; b++)
            #pragma unroll
            for (int c = 0; c < 4; c++) {
                accN[a][b][c] = 0.f; accG[a][b][c] = 0.f;
                accP[a][b][c] = 0.f; accQ[a][b][c] = 0.f;
            }

    // ---- stage loader: 2 MH tiles (A rows=ib, B rows=jb) x 64 rows x 16 chunks
    auto load_stage = [&](int stage, int kt) {
        unsigned sb = sb0 + stage * STAGE_BYTES;
        int kcol = kt * BK;
        #pragma unroll
        for (int it = 0; it < 16; it++) {          // 2*64*16 = 2048 chunks / 128 thr
            int id = tid + it * 128;
            int op = id >> 10;                     // 0..1
            int rem = id & 1023, r = rem >> 4, c = rem & 15;
            int rowbase = op ? jb : ib;
            const __nv_bfloat16* gp = g_MH + (size_t)(rowbase + r) * D_DIM + kcol + c * 8;
            cp_async16(sb + op * OP_BYTES + r * 256 + swz(c, r), gp);
        }
    };

    // ldmatrix per-lane geometry
    const int a_lrow = lane & 15;
    const int a_half = lane >> 4;
    const int b_lrow = (lane & 7) + ((lane >> 4) << 3);
    const int b_half = (lane >> 3) & 1;

    load_stage(0, 0); cp_commit();
    load_stage(1, 1); cp_commit();

    #pragma unroll 1
    for (int kt = 0; kt < NT; kt++) {
        if (kt < NT - 1) cp_wait1(); else cp_wait0();   // stage kt resident
        __syncthreads();                                 // kt-1 consumption done
        if (kt + 2 < NT) { load_stage((kt + 2) % NSTAGE, kt + 2); cp_commit(); }

        unsigned sb = sb0 + (kt % NSTAGE) * STAGE_BYTES;
        #pragma unroll
        for (int kk8 = 0; kk8 < 16; kk8 += 2) {      // 8 k-chunks of 16
            // B fragments: MH + derived Mb, MH2, MS (4 nf x 2 regs each)
            unsigned bMH[4][2], bMb[4][2], bMH2[4][2], bMS[4][2];
            #pragma unroll
            for (int ng = 0; ng < 2; ng++) {
                int row = wn * 32 + ng * 16 + b_lrow;
                unsigned addr = sb + B_OFF + row * 256 + swz(kk8 + b_half, row);
                unsigned r[4]; ldsm_x4(r, addr);
                bMH[2 * ng][0] = r[0]; bMH[2 * ng][1] = r[1];
                bMH[2 * ng + 1][0] = r[2]; bMH[2 * ng + 1][1] = r[3];
            }
            #pragma unroll
            for (int nf = 0; nf < 4; nf++)
                #pragma unroll
                for (int rr = 0; rr < 2; rr++) {
                    unsigned mh = bMH[nf][rr];
                    unsigned mb = hne2z(mh);
                    bMb[nf][rr]  = mb;
                    bMS[nf][rr]  = hsub2u(mh, mb);
                    bMH2[nf][rr] = hmul2u(mh, mh);
                }
            // A fragments per mf row-slab
            #pragma unroll
            for (int mf = 0; mf < 2; mf++) {
                int row = wm * 32 + mf * 16 + a_lrow;
                unsigned arow_off = row * 256 + swz(kk8 + a_half, row);
                unsigned aMH[4]; ldsm_x4(aMH, sb + arow_off);
                unsigned aMb[4], aPS[4], aMH2[4];
                #pragma unroll
                for (int q = 0; q < 4; q++) {
                    aMb[q]  = hne2z(aMH[q]);
                    aPS[q]  = hadd2u(aMH[q], aMb[q]);
                    aMH2[q] = hmul2u(aMH[q], aMH[q]);
                }
                #pragma unroll
                for (int nf = 0; nf < 4; nf++) {
                    mma16816(accN[mf][nf], aMb,  bMb[nf]);    // n += Mb.Mb
                    mma16816(accG[mf][nf], aMH,  bMH[nf]);    // G += MH.MH
                    mma16816(accP[mf][nf], aPS,  bMS[nf]);    // P += (MH+Mb).(MH-Mb)
                    mma16816(accQ[mf][nf], aMb,  bMH2[nf]);   // Q += Mb.MH2
                    mma16816(accQ[mf][nf], aMH2, bMb[nf]);    // Q += MH2.Mb
                }
            }
        }
    }

    // ---- epilogue: score + packed (score,index) min-reduction --------------
    unsigned long long rk[2][2] = {{~0ull, ~0ull}, {~0ull, ~0ull}};   // [mf][rr]
    unsigned long long ck[4][2] = {{~0ull,~0ull},{~0ull,~0ull},{~0ull,~0ull},{~0ull,~0ull}};

    #pragma unroll
    for (int mf = 0; mf < 2; mf++) {
        const int i0 = ib + wm * 32 + mf * 16 + g;
        const int am0 = g_am[i0];
        const int am1 = g_am[i0 + 8];
        #pragma unroll
        for (int nf = 0; nf < 4; nf++)
            #pragma unroll
            for (int idx = 0; idx < 4; idx++) {
                int rr = idx >> 1, c = idx & 1;
                int i = i0 + rr * 8;
                int jl = wn * 32 + nf * 8 + tg * 2 + c;
                int j = jb + jl;
                float nn = accN[mf][nf][idx];
                int ami = rr ? am1 : am0;
                if (i != j && nn > 1.5f && ami != s_amJ[jl]) {
                    float ns = fmaxf(nn, 2.f);
                    float gg = accG[mf][nf][idx];
                    float s1 = gg - nn - accP[mf][nf][idx];
                    float s2 = accQ[mf][nf][idx] - 2.f * gg;
                    float var = (s2 - s1 * s1 / ns) / (ns - 1.f);
                    rk[mf][rr] = ullmin2(rk[mf][rr], pack_key(var, j));
                    ck[nf][c]  = ullmin2(ck[nf][c],  pack_key(var, i));
                }
            }
    }

    // row-side: min over quad lanes (same row, different cols)
    #pragma unroll
    for (int mf = 0; mf < 2; mf++)
        #pragma unroll
        for (int rr = 0; rr < 2; rr++) {
            unsigned long long v = rk[mf][rr];
            v = ullmin2(v, __shfl_xor_sync(0xffffffffu, v, 1));
            v = ullmin2(v, __shfl_xor_sync(0xffffffffu, v, 2));
            if (tg == 0 && v != ~0ull)
                atomicMin(&keyI[wm * 32 + mf * 16 + rr * 8 + g], v);
        }
    // col-side: min over lanes sharing tg (same cols, different rows)
    #pragma unroll
    for (int nf = 0; nf < 4; nf++)
        #pragma unroll
        for (int c = 0; c < 2; c++) {
            unsigned long long v = ck[nf][c];
            v = ullmin2(v, __shfl_down_sync(0xffffffffu, v, 4));
            v = ullmin2(v, __shfl_down_sync(0xffffffffu, v, 8));
            v = ullmin2(v, __shfl_down_sync(0xffffffffu, v, 16));
            if (g == 0 && v != ~0ull)
                atomicMin(&keyJ[wn * 32 + nf * 8 + tg * 2 + c], v);
        }

    __syncthreads();
    if (tid < BM) {
        if (keyI[tid] != ~0ull) atomicMin(&g_rowmin[ib + tid], keyI[tid]);
    } else {
        if (keyJ[tid - BM] != ~0ull) atomicMin(&g_rowmin[jb + tid - BM], keyJ[tid - BM]);
    }
}

// ---------------- kernel 3: row loss + last-block final combine -------------
__global__ void rowloss_kernel(const float* __restrict__ H, float* __restrict__ out) {
    int warp = threadIdx.x >> 5;                   // 4 warps/block
    int lane = threadIdx.x & 31;
    int t = threadIdx.x;
    int i = blockIdx.x * 4 + warp;
    int j = (int)(g_rowmin[i] & 0xFFFFFFFFull);
    const float* ri = H + (size_t)i * D_DIM;
    const float* rj = H + (size_t)j * D_DIM;
    float s = 0.f;
    #pragma unroll
    for (int it = 0; it < 8; it++) {               // 8 x 32 lanes x float4 = 1024
        float4 va = *(const float4*)(ri + it * 128 + lane * 4);
        float4 vb = *(const float4*)(rj + it * 128 + lane * 4);
        float dx = va.x - vb.x, dy = va.y - vb.y, dz = va.z - vb.z, dw = va.w - vb.w;
        s += dx * dx + dy * dy + dz * dz + dw * dw;
    }
    #pragma unroll
    for (int off = 16; off > 0; off >>= 1)
        s += __shfl_xor_sync(0xffffffffu, s, off);
    if (lane == 0) g_rowlossp[i] = (float)sqrt((double)s);

    // ---- last block performs the final combine -----------------------------
    __shared__ unsigned s_last;
    __syncthreads();
    if (t == 0) {
        __threadfence();                           // partials visible chip-wide
        unsigned old = atomicAdd(&g_done, 1u);
        s_last = (old == RL_BLOCKS - 1) ? 1u : 0u;
    }
    __syncthreads();
    if (s_last) {
        double sm = 0.0, sr = 0.0;
        #pragma unroll
        for (int q = 0; q < T_DIM / 128; q++) {    // 32 elems per thread, coalesced
            int k = t + q * 128;
            sm += (double)g_msep[k];
            sr += (double)g_rowlossp[k];
        }
        #pragma unroll
        for (int off = 16; off > 0; off >>= 1) {
            sm += __shfl_xor_sync(0xffffffffu, sm, off);
            sr += __shfl_xor_sync(0xffffffffu, sr, off);
        }
        __shared__ double shm[4], shr[4];
        if (lane == 0) { shm[warp] = sm; shr[warp] = sr; }
        __syncthreads();
        if (t == 0) {
            double tm = shm[0] + shm[1] + shm[2] + shm[3];
            double tr = shr[0] + shr[1] + shr[2] + shr[3];
            out[0] = (float)(tm + 10.0 * tr);
            g_done = 0;                            // reset for next graph replay
        }
    }
}

// ---------------- launch ------------------------------------------------------
extern "C" void kernel_launch(void* const* d_in, const int* in_sizes, int n_in,
                              void* d_out, int out_size) {
    const float* X = (const float*)d_in[0];
    const float* H = (const float*)d_in[1];
    const float* C = (const float*)d_in[2];
    const float* M = (const float*)d_in[3];
    (void)in_sizes; (void)n_in; (void)out_size;

    cudaFuncSetAttribute(gemm_kernel, cudaFuncAttributeMaxDynamicSharedMemorySize, SMEM_REQ);

    prep_kernel<<<T_DIM, 256>>>(X, H, C, M);
    dim3 grid(NTILE + 1, NTILE / 2);               // (65, 32) exact triangle cover
    gemm_kernel<<<grid, 128, SMEM_REQ>>>();
    rowloss_kernel<<<RL_BLOCKS, 128>>>(H, (float*)d_out);
}